// round 1
// baseline (speedup 1.0000x reference)
#include <cuda_runtime.h>
#include <math.h>

// ---------------- problem constants ----------------
#define BB   8
#define C0   512
#define HW0  64
#define N0   64
#define L0   8
#define KN0  4
#define C1   64
#define HW1  16384
#define N1   512
#define L1   80
#define KN1  40
#define M1   41          // 1 center + 40
#define NS0  (BB*N0)     // 512 samples path0
#define NS1  (BB*N1)     // 4096 samples path1
#define ROWS1 (NS1*M1)   // 167936
#define H1   1024
#define O0   256
#define O1   256

// ---------------- scratch (static device arrays; no allocs) ----------------
__device__ float g_fr0[BB*HW0*C0];      // transposed feat0: (b, p, c)
__device__ float g_fr1[BB*HW1*C1];      // transposed feat1: (b, p, c)
__device__ float g_X0[NS0*C0];
__device__ float g_H [NS0*H1];
__device__ float g_A [NS0*H1];
__device__ float g_scale[H1];
__device__ float g_shift[H1];
__device__ float g_X1[(long)ROWS1*C1];  // gathered rows for path1

// ---------------- transpose (b,c,p) -> (b,p,c) ----------------
__global__ void transpose_feat(const float* __restrict__ f, float* __restrict__ out,
                               int Bc, int Cc, int P) {
    long total = (long)Bc * Cc * P;
    for (long i = (long)blockIdx.x * blockDim.x + threadIdx.x; i < total;
         i += (long)gridDim.x * blockDim.x) {
        int  p = (int)(i % P);
        long t = i / P;
        int  c = (int)(t % Cc);
        int  b = (int)(t / Cc);
        out[((long)b * P + p) * Cc + c] = f[i];
    }
}

// ---------------- path0 sampling: top-4 of 8, mean of 5 rows ----------------
__global__ void sample0_kernel(const int* __restrict__ pid, const int* __restrict__ lid) {
    __shared__ float cen[C0];
    __shared__ float sim[L0];
    __shared__ int   rowsS[L0];
    __shared__ int   chosen[KN0];
    int blk = blockIdx.x;            // 0..511
    int b = blk / N0, n = blk % N0;
    int t = threadIdx.x;             // 256 threads
    int p = pid[n];
    const float* base = g_fr0 + (long)b * HW0 * C0;
    const float* cptr = base + (long)p * C0;
    for (int c = t; c < C0; c += 256) cen[c] = cptr[c];
    if (t < L0) rowsS[t] = lid[n * L0 + t];
    __syncthreads();
    int w = t >> 5, lane = t & 31;   // 8 warps, one per neighbor
    {
        const float* lp = base + (long)rowsS[w] * C0;
        float dot = 0.f, ss = 0.f;
        for (int c = lane; c < C0; c += 32) {
            float v = lp[c];
            dot += v * cen[c];
            ss  += v * v;
        }
        for (int o = 16; o > 0; o >>= 1) {
            dot += __shfl_down_sync(0xffffffffu, dot, o);
            ss  += __shfl_down_sync(0xffffffffu, ss,  o);
        }
        if (lane == 0) sim[w] = dot / fmaxf(sqrtf(ss), 1e-12f);
    }
    __syncthreads();
    if (t == 0) {
        bool used[L0];
        for (int l = 0; l < L0; l++) used[l] = false;
        for (int r = 0; r < KN0; r++) {
            int bi = -1; float bv = -1e30f;
            for (int l = 0; l < L0; l++)
                if (!used[l] && sim[l] > bv) { bv = sim[l]; bi = l; }
            used[bi] = true;
            chosen[r] = rowsS[bi];
        }
    }
    __syncthreads();
    for (int c = t; c < C0; c += 256) {
        float acc = cen[c];
        #pragma unroll
        for (int r = 0; r < KN0; r++) acc += base[(long)chosen[r] * C0 + c];
        g_X0[(long)blk * C0 + c] = acc * 0.2f;
    }
}

// ---------------- path1 sampling: top-40 of 80 (jax ordering), gather 41 rows ----------------
__global__ void sample1_kernel(const int* __restrict__ pid, const int* __restrict__ lid) {
    __shared__ float cen[C1];
    __shared__ float sim[L1];
    __shared__ int   rowsS[L1];
    __shared__ int   sel[KN1];
    int blk = blockIdx.x;            // 0..4095
    int b = blk / N1, n = blk % N1;
    int t = threadIdx.x;             // 128 threads
    const float* base = g_fr1 + (long)b * HW1 * C1;
    int p = pid[n];
    if (t < C1) cen[t] = base[(long)p * C1 + t];
    if (t < L1) rowsS[t] = lid[n * L1 + t];
    __syncthreads();
    int w = t >> 5, lane = t & 31;   // 4 warps
    for (int l = w; l < L1; l += 4) {
        const float* lp = base + (long)rowsS[l] * C1;
        float v0 = lp[lane], v1 = lp[lane + 32];
        float dot = v0 * cen[lane] + v1 * cen[lane + 32];
        float ss  = v0 * v0 + v1 * v1;
        for (int o = 16; o > 0; o >>= 1) {
            dot += __shfl_down_sync(0xffffffffu, dot, o);
            ss  += __shfl_down_sync(0xffffffffu, ss,  o);
        }
        if (lane == 0) sim[l] = dot / fmaxf(sqrtf(ss), 1e-12f);
    }
    __syncthreads();
    if (w == 0) {
        for (int r = 0; r < KN1; r++) {
            float bv = -1e30f; int bi = 0x7fffffff;
            for (int l = lane; l < L1; l += 32) {
                float v = sim[l];
                if (v > bv || (v == bv && l < bi)) { bv = v; bi = l; }
            }
            for (int o = 16; o > 0; o >>= 1) {
                float ov = __shfl_down_sync(0xffffffffu, bv, o);
                int   oi = __shfl_down_sync(0xffffffffu, bi, o);
                if (ov > bv || (ov == bv && oi < bi)) { bv = ov; bi = oi; }
            }
            bi = __shfl_sync(0xffffffffu, bi, 0);
            if (lane == 0) sel[r] = bi;
            sim[bi] = -1e38f;           // mark used (all lanes, same value)
            __syncwarp();
        }
    }
    __syncthreads();
    long obase = (long)blk * M1 * C1;
    for (int idx = t; idx < M1 * C1; idx += 128) {
        int m = idx / C1, c = idx % C1;
        int src = (m == 0) ? p : rowsS[sel[m - 1]];
        g_X1[obase + idx] = base[(long)src * C1 + c];
    }
}

// ---------------- generic tiled SGEMM: C[M,N] = A[M,K] @ Bw[N,K]^T + bias[N] ----------------
__global__ __launch_bounds__(256) void sgemm_bias(const float* __restrict__ A,
                                                  const float* __restrict__ Bw,
                                                  const float* __restrict__ bias,
                                                  float* __restrict__ C,
                                                  int M, int N, int K) {
    __shared__ float As[64 * 16];
    __shared__ float Bs[16 * 64];
    int t = threadIdx.x;
    int tx = t & 15, ty = t >> 4;
    int m0 = blockIdx.y * 64, n0 = blockIdx.x * 64;
    float acc[4][4];
    #pragma unroll
    for (int i = 0; i < 4; i++)
        #pragma unroll
        for (int j = 0; j < 4; j++) acc[i][j] = 0.f;

    for (int k0 = 0; k0 < K; k0 += 16) {
        __syncthreads();
        for (int idx = t; idx < 1024; idx += 256) {
            int m = idx >> 4, kk = idx & 15;
            As[m * 16 + kk] = A[(long)(m0 + m) * K + k0 + kk];
        }
        for (int idx = t; idx < 1024; idx += 256) {
            int kk = idx >> 6, n = idx & 63;
            Bs[kk * 64 + n] = Bw[(long)(n0 + n) * K + k0 + kk];
        }
        __syncthreads();
        #pragma unroll
        for (int kk = 0; kk < 16; kk++) {
            float a[4], bv[4];
            #pragma unroll
            for (int i = 0; i < 4; i++) a[i] = As[(ty + 16 * i) * 16 + kk];
            #pragma unroll
            for (int j = 0; j < 4; j++) bv[j] = Bs[kk * 64 + tx + 16 * j];
            #pragma unroll
            for (int i = 0; i < 4; i++)
                #pragma unroll
                for (int j = 0; j < 4; j++) acc[i][j] += a[i] * bv[j];
        }
    }
    #pragma unroll
    for (int j = 0; j < 4; j++) {
        float bj = bias[n0 + tx + 16 * j];
        #pragma unroll
        for (int i = 0; i < 4; i++)
            C[(long)(m0 + ty + 16 * i) * N + n0 + tx + 16 * j] = acc[i][j] + bj;
    }
}

// ---------------- BN stats: per-column mean/var over 512 rows -> scale/shift ----------------
__global__ void bnstats_kernel(const float* __restrict__ gamma, const float* __restrict__ beta) {
    int j = blockIdx.x;      // 0..1023
    int t = threadIdx.x;     // 128
    float s = 0.f, ss = 0.f;
    for (int r = t; r < NS0; r += 128) {
        float v = g_H[(long)r * H1 + j];
        s += v; ss += v * v;
    }
    __shared__ float sm[128], sm2[128];
    sm[t] = s; sm2[t] = ss;
    __syncthreads();
    for (int o = 64; o > 0; o >>= 1) {
        if (t < o) { sm[t] += sm[t + o]; sm2[t] += sm2[t + o]; }
        __syncthreads();
    }
    if (t == 0) {
        float mu  = sm[0] / NS0;
        float var = sm2[0] / NS0 - mu * mu;
        float sc  = gamma[j] / sqrtf(var + 1e-5f);
        g_scale[j] = sc;
        g_shift[j] = beta[j] - mu * sc;
    }
}

__global__ void bnapply_kernel() {
    long total = (long)NS0 * H1;
    for (long i = (long)blockIdx.x * blockDim.x + threadIdx.x; i < total;
         i += (long)gridDim.x * blockDim.x) {
        int j = (int)(i % H1);
        float v = g_H[i] * g_scale[j] + g_shift[j];
        g_A[i] = fmaxf(v, 0.f);
    }
}

// ---------------- big fused MLP: relu(X@W3^T+b3)@W4^T+b4, row L2 norm ----------------
// 128 rows per block, 256 threads. smem: sX[128*64] sH[128*257] sW[32*257] rss[128*16]
#define MT 128
#define SHP 257
__global__ __launch_bounds__(256) void mlp_kernel(const float* __restrict__ W3,
                                                  const float* __restrict__ b3,
                                                  const float* __restrict__ W4,
                                                  const float* __restrict__ b4,
                                                  float* __restrict__ out1) {
    extern __shared__ float smem[];
    float* sX  = smem;                 // 8192
    float* sH  = sX + MT * 64;         // 128*257 = 32896
    float* sW  = sH + MT * SHP;        // 32*257 = 8224
    float* rss = sW + 32 * SHP;        // 128*16 = 2048

    int t = threadIdx.x;
    long row0 = (long)blockIdx.x * MT;

    // load X tile (coalesced)
    const float4* Xg = (const float4*)(g_X1 + row0 * 64);
    float4* sX4 = (float4*)sX;
    for (int i = t; i < MT * 16; i += 256) sX4[i] = Xg[i];

    // stage 1: thread t owns hidden unit t; W3 row in registers
    float4 w3r[16];
    const float4* w3g = (const float4*)(W3 + t * 64);
    #pragma unroll
    for (int c = 0; c < 16; c++) w3r[c] = w3g[c];
    float bb3 = b3[t];
    __syncthreads();

    for (int r = 0; r < MT; r++) {
        const float4* xr = (const float4*)(sX + r * 64);
        float a0 = 0.f, a1 = 0.f, a2 = 0.f, a3 = 0.f;
        #pragma unroll
        for (int c = 0; c < 16; c++) {
            float4 x = xr[c];
            a0 += w3r[c].x * x.x;
            a1 += w3r[c].y * x.y;
            a2 += w3r[c].z * x.z;
            a3 += w3r[c].w * x.w;
        }
        sH[r * SHP + t] = fmaxf(a0 + a1 + a2 + a3 + bb3, 0.f);
    }
    __syncthreads();

    // stage 2: 128x256 output tile, thread (ty,tx) -> rows ty*8..+7, cols tx+16*j
    int tx = t & 15, ty = t >> 4;
    int rb = ty * 8;
    float acc[8][16];
    #pragma unroll
    for (int i = 0; i < 8; i++)
        #pragma unroll
        for (int j = 0; j < 16; j++) acc[i][j] = 0.f;

    for (int k0 = 0; k0 < 256; k0 += 32) {
        __syncthreads();
        // stage W4 slice: sW[kk*257 + j] = W4[j*256 + k0+kk]   (coalesced gmem, conflict-free smem)
        for (int idx = t; idx < 8192; idx += 256) {
            int j = idx >> 5, kk = idx & 31;
            sW[kk * SHP + j] = W4[(long)j * 256 + k0 + kk];
        }
        __syncthreads();
        #pragma unroll 4
        for (int kk = 0; kk < 32; kk++) {
            float a[8];
            #pragma unroll
            for (int i = 0; i < 8; i++) a[i] = sH[(rb + i) * SHP + (k0 + kk)];
            float wv[16];
            #pragma unroll
            for (int j = 0; j < 16; j++) wv[j] = sW[kk * SHP + tx + 16 * j];
            #pragma unroll
            for (int i = 0; i < 8; i++)
                #pragma unroll
                for (int j = 0; j < 16; j++) acc[i][j] += a[i] * wv[j];
        }
    }

    // epilogue: + b4, deterministic row L2 norm, write out
    float myb4[16];
    #pragma unroll
    for (int j = 0; j < 16; j++) myb4[j] = b4[tx + 16 * j];
    #pragma unroll
    for (int i = 0; i < 8; i++) {
        float s = 0.f;
        #pragma unroll
        for (int j = 0; j < 16; j++) {
            float y = acc[i][j] + myb4[j];
            acc[i][j] = y;
            s += y * y;
        }
        rss[(rb + i) * 16 + tx] = s;
    }
    __syncthreads();
    float* rnorm = sX;  // reuse (sX dead after stage 1)
    if (t < MT) {
        float s = 0.f;
        #pragma unroll
        for (int q = 0; q < 16; q++) s += rss[t * 16 + q];
        rnorm[t] = 1.f / (sqrtf(s) + 1e-7f);
    }
    __syncthreads();
    #pragma unroll
    for (int i = 0; i < 8; i++) {
        float rn = rnorm[rb + i];
        long gr = row0 + rb + i;
        #pragma unroll
        for (int j = 0; j < 16; j++)
            out1[gr * 256 + tx + 16 * j] = acc[i][j] * rn;
    }
}

// ---------------- host launcher ----------------
extern "C" void kernel_launch(void* const* d_in, const int* in_sizes, int n_in,
                              void* d_out, int out_size) {
    const float* feat0 = (const float*)d_in[0];
    const float* feat1 = (const float*)d_in[1];
    const float* W1    = (const float*)d_in[2];
    const float* b1    = (const float*)d_in[3];
    const float* gamma = (const float*)d_in[4];
    const float* beta  = (const float*)d_in[5];
    const float* W2    = (const float*)d_in[6];
    const float* b2    = (const float*)d_in[7];
    const float* W3    = (const float*)d_in[8];
    const float* b3    = (const float*)d_in[9];
    const float* W4    = (const float*)d_in[10];
    const float* b4    = (const float*)d_in[11];
    const int* patch_id0 = (const int*)d_in[12];
    const int* patch_id1 = (const int*)d_in[13];
    const int* local_id0 = (const int*)d_in[14];
    const int* local_id1 = (const int*)d_in[15];
    (void)in_sizes; (void)n_in; (void)out_size;

    float* out0 = (float*)d_out;
    float* out1 = out0 + (long)NS0 * O0;

    float* fr0; cudaGetSymbolAddress((void**)&fr0, g_fr0);
    float* fr1; cudaGetSymbolAddress((void**)&fr1, g_fr1);
    float* X0;  cudaGetSymbolAddress((void**)&X0,  g_X0);
    float* H;   cudaGetSymbolAddress((void**)&H,   g_H);
    float* Ab;  cudaGetSymbolAddress((void**)&Ab,  g_A);

    int smem_mlp = (MT * 64 + MT * SHP + 32 * SHP + MT * 16) * 4;
    cudaFuncSetAttribute(mlp_kernel, cudaFuncAttributeMaxDynamicSharedMemorySize, smem_mlp);

    // transposes
    transpose_feat<<<512, 256>>>(feat0, fr0, BB, C0, HW0);
    transpose_feat<<<4096, 256>>>(feat1, fr1, BB, C1, HW1);

    // path0
    sample0_kernel<<<NS0, 256>>>(patch_id0, local_id0);
    {
        dim3 g(H1 / 64, NS0 / 64);
        sgemm_bias<<<g, 256>>>(X0, W1, b1, H, NS0, H1, C0);
    }
    bnstats_kernel<<<H1, 128>>>(gamma, beta);
    bnapply_kernel<<<1024, 256>>>();
    {
        dim3 g(O0 / 64, NS0 / 64);
        sgemm_bias<<<g, 256>>>(Ab, W2, b2, out0, NS0, O0, H1);
    }

    // path1
    sample1_kernel<<<NS1, 128>>>(patch_id1, local_id1);
    mlp_kernel<<<ROWS1 / MT, 256, smem_mlp>>>(W3, b3, W4, b4, out1);
}

// round 3
// speedup vs baseline: 2.3689x; 2.3689x over previous
#include <cuda_runtime.h>
#include <math.h>
#include <stdint.h>

// ---------------- problem constants ----------------
#define BB   8
#define C0   512
#define HW0  64
#define N0   64
#define L0   8
#define KN0  4
#define C1   64
#define HW1  16384
#define N1   512
#define L1   80
#define KN1  40
#define M1   41          // 1 center + 40
#define NS0  (BB*N0)     // 512 samples path0
#define NS1  (BB*N1)     // 4096 samples path1
#define ROWS1 (NS1*M1)   // 167936
#define H1   1024
#define O0   256
#define O1   256

// ---------------- scratch (static device arrays; no allocs) ----------------
__device__ float g_fr0[BB*HW0*C0];      // transposed feat0: (b, p, c)
__device__ float g_fr1[BB*HW1*C1];      // transposed feat1: (b, p, c)
__device__ float g_X0[NS0*C0];
__device__ float g_H [NS0*H1];
__device__ float g_A [NS0*H1];
__device__ float g_scale[H1];
__device__ float g_shift[H1];
__device__ float g_X1[(long)ROWS1*C1];  // gathered rows for path1
__device__ float g_P [4*512*1024];      // split-K partials (8MB, reused)

// ================= tf32 helpers (compute_80-level PTX only) =================
__device__ __forceinline__ float tf32r(float x) {
    uint32_t u;
    asm("cvt.rna.tf32.f32 %0, %1;" : "=r"(u) : "f"(x));
    return __uint_as_float(u);
}
__device__ __forceinline__ float4 tf4(float4 v) {
    v.x = tf32r(v.x); v.y = tf32r(v.y); v.z = tf32r(v.z); v.w = tf32r(v.w);
    return v;
}
__device__ __forceinline__ void mma8(float acc[4], float a0, float a1, float a2, float a3,
                                     float b0, float b1) {
    asm volatile(
        "mma.sync.aligned.m16n8k8.row.col.f32.tf32.tf32.f32 "
        "{%0,%1,%2,%3}, {%4,%5,%6,%7}, {%8,%9}, {%0,%1,%2,%3};"
        : "+f"(acc[0]), "+f"(acc[1]), "+f"(acc[2]), "+f"(acc[3])
        : "r"(__float_as_uint(a0)), "r"(__float_as_uint(a1)),
          "r"(__float_as_uint(a2)), "r"(__float_as_uint(a3)),
          "r"(__float_as_uint(b0)), "r"(__float_as_uint(b1)));
}
// k-pair reorder within each 8-block: col k stored at pos ((k&3)<<1)|(k>>2),
// so (k, k+4) are adjacent -> fragment loads become single lds.64.
__device__ __forceinline__ int kpos(int k) { return ((k & 3) << 1) | (k >> 2); }
__device__ __forceinline__ void st_reord4(float* rowp, int k0, float4 v) {
    rowp[((k0  ) >> 3) * 8 + kpos((k0  ) & 7)] = v.x;
    rowp[((k0+1) >> 3) * 8 + kpos((k0+1) & 7)] = v.y;
    rowp[((k0+2) >> 3) * 8 + kpos((k0+2) & 7)] = v.z;
    rowp[((k0+3) >> 3) * 8 + kpos((k0+3) & 7)] = v.w;
}

// ---------------- transpose (b,c,p) -> (b,p,c) ----------------
__global__ void transpose_feat(const float* __restrict__ f, float* __restrict__ out,
                               int Bc, int Cc, int P) {
    long total = (long)Bc * Cc * P;
    for (long i = (long)blockIdx.x * blockDim.x + threadIdx.x; i < total;
         i += (long)gridDim.x * blockDim.x) {
        int  p = (int)(i % P);
        long t = i / P;
        int  c = (int)(t % Cc);
        int  b = (int)(t / Cc);
        out[((long)b * P + p) * Cc + c] = f[i];
    }
}

// ---------------- path0 sampling ----------------
__global__ void sample0_kernel(const int* __restrict__ pid, const int* __restrict__ lid) {
    __shared__ float cen[C0];
    __shared__ float sim[L0];
    __shared__ int   rowsS[L0];
    __shared__ int   chosen[KN0];
    int blk = blockIdx.x;
    int b = blk / N0, n = blk % N0;
    int t = threadIdx.x;
    int p = pid[n];
    const float* base = g_fr0 + (long)b * HW0 * C0;
    const float* cptr = base + (long)p * C0;
    for (int c = t; c < C0; c += 256) cen[c] = cptr[c];
    if (t < L0) rowsS[t] = lid[n * L0 + t];
    __syncthreads();
    int w = t >> 5, lane = t & 31;
    {
        const float* lp = base + (long)rowsS[w] * C0;
        float dot = 0.f, ss = 0.f;
        for (int c = lane; c < C0; c += 32) {
            float v = lp[c];
            dot += v * cen[c];
            ss  += v * v;
        }
        for (int o = 16; o > 0; o >>= 1) {
            dot += __shfl_down_sync(0xffffffffu, dot, o);
            ss  += __shfl_down_sync(0xffffffffu, ss,  o);
        }
        if (lane == 0) sim[w] = dot / fmaxf(sqrtf(ss), 1e-12f);
    }
    __syncthreads();
    if (t == 0) {
        bool used[L0];
        for (int l = 0; l < L0; l++) used[l] = false;
        for (int r = 0; r < KN0; r++) {
            int bi = -1; float bv = -1e30f;
            for (int l = 0; l < L0; l++)
                if (!used[l] && sim[l] > bv) { bv = sim[l]; bi = l; }
            used[bi] = true;
            chosen[r] = rowsS[bi];
        }
    }
    __syncthreads();
    for (int c = t; c < C0; c += 256) {
        float acc = cen[c];
        #pragma unroll
        for (int r = 0; r < KN0; r++) acc += base[(long)chosen[r] * C0 + c];
        g_X0[(long)blk * C0 + c] = acc * 0.2f;
    }
}

// ---------------- path1 sampling ----------------
__global__ void sample1_kernel(const int* __restrict__ pid, const int* __restrict__ lid) {
    __shared__ float cen[C1];
    __shared__ float sim[L1];
    __shared__ int   rowsS[L1];
    __shared__ int   sel[KN1];
    int blk = blockIdx.x;
    int b = blk / N1, n = blk % N1;
    int t = threadIdx.x;
    const float* base = g_fr1 + (long)b * HW1 * C1;
    int p = pid[n];
    if (t < C1) cen[t] = base[(long)p * C1 + t];
    if (t < L1) rowsS[t] = lid[n * L1 + t];
    __syncthreads();
    int w = t >> 5, lane = t & 31;
    for (int l = w; l < L1; l += 4) {
        const float* lp = base + (long)rowsS[l] * C1;
        float v0 = lp[lane], v1 = lp[lane + 32];
        float dot = v0 * cen[lane] + v1 * cen[lane + 32];
        float ss  = v0 * v0 + v1 * v1;
        for (int o = 16; o > 0; o >>= 1) {
            dot += __shfl_down_sync(0xffffffffu, dot, o);
            ss  += __shfl_down_sync(0xffffffffu, ss,  o);
        }
        if (lane == 0) sim[l] = dot / fmaxf(sqrtf(ss), 1e-12f);
    }
    __syncthreads();
    if (w == 0) {
        for (int r = 0; r < KN1; r++) {
            float bv = -1e30f; int bi = 0x7fffffff;
            for (int l = lane; l < L1; l += 32) {
                float v = sim[l];
                if (v > bv || (v == bv && l < bi)) { bv = v; bi = l; }
            }
            for (int o = 16; o > 0; o >>= 1) {
                float ov = __shfl_down_sync(0xffffffffu, bv, o);
                int   oi = __shfl_down_sync(0xffffffffu, bi, o);
                if (ov > bv || (ov == bv && oi < bi)) { bv = ov; bi = oi; }
            }
            bi = __shfl_sync(0xffffffffu, bi, 0);
            if (lane == 0) sel[r] = bi;
            sim[bi] = -1e38f;
            __syncwarp();
        }
    }
    __syncthreads();
    long obase = (long)blk * M1 * C1;
    for (int idx = t; idx < M1 * C1; idx += 128) {
        int m = idx / C1, c = idx % C1;
        int src = (m == 0) ? p : rowsS[sel[m - 1]];
        g_X1[obase + idx] = base[(long)src * C1 + c];
    }
}

// ---------------- split-K SGEMM partial ----------------
__global__ __launch_bounds__(256) void sgemm_sk(const float* __restrict__ A,
                                                const float* __restrict__ Bw,
                                                float* __restrict__ P,
                                                int M, int N, int K, int KC) {
    __shared__ float As[64 * 16];
    __shared__ float Bs[16 * 64];
    int t = threadIdx.x;
    int tx = t & 15, ty = t >> 4;
    int m0 = blockIdx.y * 64, n0 = blockIdx.x * 64;
    int s  = blockIdx.z;
    int kb = s * KC, ke = kb + KC;
    float acc[4][4];
    #pragma unroll
    for (int i = 0; i < 4; i++)
        #pragma unroll
        for (int j = 0; j < 4; j++) acc[i][j] = 0.f;

    for (int k0 = kb; k0 < ke; k0 += 16) {
        __syncthreads();
        for (int idx = t; idx < 1024; idx += 256) {
            int m = idx >> 4, kk = idx & 15;
            As[m * 16 + kk] = A[(long)(m0 + m) * K + k0 + kk];
        }
        for (int idx = t; idx < 1024; idx += 256) {
            int kk = idx >> 6, n = idx & 63;
            Bs[kk * 64 + n] = Bw[(long)(n0 + n) * K + k0 + kk];
        }
        __syncthreads();
        #pragma unroll
        for (int kk = 0; kk < 16; kk++) {
            float a[4], bv[4];
            #pragma unroll
            for (int i = 0; i < 4; i++) a[i] = As[(ty + 16 * i) * 16 + kk];
            #pragma unroll
            for (int j = 0; j < 4; j++) bv[j] = Bs[kk * 64 + tx + 16 * j];
            #pragma unroll
            for (int i = 0; i < 4; i++)
                #pragma unroll
                for (int j = 0; j < 4; j++) acc[i][j] += a[i] * bv[j];
        }
    }
    long base = (long)s * M * N;
    #pragma unroll
    for (int j = 0; j < 4; j++)
        #pragma unroll
        for (int i = 0; i < 4; i++)
            P[base + (long)(m0 + ty + 16 * i) * N + n0 + tx + 16 * j] = acc[i][j];
}

__global__ void reduce_bias(const float* __restrict__ P, const float* __restrict__ bias,
                            float* __restrict__ C, int M, int N, int S) {
    long MN = (long)M * N;
    for (long i = (long)blockIdx.x * blockDim.x + threadIdx.x; i < MN;
         i += (long)gridDim.x * blockDim.x) {
        float acc = 0.f;
        for (int s = 0; s < S; s++) acc += P[(long)s * MN + i];
        C[i] = acc + bias[i % N];
    }
}

// ---------------- BN ----------------
__global__ void bnstats_kernel(const float* __restrict__ gamma, const float* __restrict__ beta) {
    int j = blockIdx.x;
    int t = threadIdx.x;
    float s = 0.f, ss = 0.f;
    for (int r = t; r < NS0; r += 128) {
        float v = g_H[(long)r * H1 + j];
        s += v; ss += v * v;
    }
    __shared__ float sm[128], sm2[128];
    sm[t] = s; sm2[t] = ss;
    __syncthreads();
    for (int o = 64; o > 0; o >>= 1) {
        if (t < o) { sm[t] += sm[t + o]; sm2[t] += sm2[t + o]; }
        __syncthreads();
    }
    if (t == 0) {
        float mu  = sm[0] / NS0;
        float var = sm2[0] / NS0 - mu * mu;
        float sc  = gamma[j] / sqrtf(var + 1e-5f);
        g_scale[j] = sc;
        g_shift[j] = beta[j] - mu * sc;
    }
}

__global__ void bnapply_kernel() {
    long total = (long)NS0 * H1;
    for (long i = (long)blockIdx.x * blockDim.x + threadIdx.x; i < total;
         i += (long)gridDim.x * blockDim.x) {
        int j = (int)(i % H1);
        float v = g_H[i] * g_scale[j] + g_shift[j];
        g_A[i] = fmaxf(v, 0.f);
    }
}

// ================= fused path1 MLP via mma.sync tf32 =================
// 128 rows/CTA, 256 threads (8 warps, warp w owns rows 16w..16w+15).
// smem (floats):
//   sH  [128][264]  offset 0        (stage1 output / stage2 A / final Y staging)
//   sP0 [10240]     offset 33792    (phase1: sX 128x72 ; phase2: W4 buf0 256x40)
//   sP1 [10240]     offset 44032    (phase1: W3 half 128x72 ; phase2: W4 buf1)
//   sb3[256] sb4[256] srn[128]
#define SHS 264
#define SXS 72
#define SW3S 72
#define SWS 40
#define SMEM_FLOATS (33792 + 10240 + 10240 + 256 + 256 + 128)

__global__ __launch_bounds__(256, 1) void mlp_mma_kernel(const float* __restrict__ W3,
                                                         const float* __restrict__ b3,
                                                         const float* __restrict__ W4,
                                                         const float* __restrict__ b4,
                                                         float* __restrict__ out1) {
    extern __shared__ float sm[];
    float* sH  = sm;
    float* sP0 = sm + 33792;
    float* sP1 = sm + 44032;
    float* sb3 = sm + 54272;
    float* sb4 = sm + 54528;
    float* srn = sm + 54784;

    int t = threadIdx.x;
    int w = t >> 5, lane = t & 31;
    int g = lane >> 2, tg = lane & 3;
    int rw0 = w * 16;
    long row0 = (long)blockIdx.x * 128;

    sb3[t] = b3[t];
    sb4[t] = b4[t];

    // ---- load X (128x64) into sP0, tf32 + k-reordered ----
    {
        const float4* Xg = (const float4*)(g_X1 + row0 * 64);
        for (int i = t; i < 2048; i += 256) {
            int r = i >> 4, cq = i & 15;
            st_reord4(sP0 + r * SXS, cq * 4, tf4(Xg[i]));
        }
    }

    // ================= stage 1: H = relu(X @ W3^T + b3) =================
    const float4* W3g = (const float4*)W3;
    #pragma unroll 1
    for (int h = 0; h < 2; h++) {
        __syncthreads();
        // load W3 half h (rows 128h..128h+127, 64 k) into sP1
        for (int i = t; i < 2048; i += 256) {
            int n = i >> 4, cq = i & 15;
            st_reord4(sP1 + n * SW3S, cq * 4, tf4(W3g[(h * 128 + n) * 16 + cq]));
        }
        __syncthreads();

        float acc1[16][4];
        #pragma unroll
        for (int nt = 0; nt < 16; nt++)
            #pragma unroll
            for (int q = 0; q < 4; q++) acc1[nt][q] = 0.f;

        #pragma unroll
        for (int ks = 0; ks < 8; ks++) {
            float2 a01 = *(const float2*)(sP0 + (rw0 + g) * SXS + ks * 8 + 2 * tg);
            float2 a23 = *(const float2*)(sP0 + (rw0 + g + 8) * SXS + ks * 8 + 2 * tg);
            #pragma unroll
            for (int nt = 0; nt < 16; nt++) {
                float2 bb = *(const float2*)(sP1 + (nt * 8 + g) * SW3S + ks * 8 + 2 * tg);
                mma8(acc1[nt], a01.x, a23.x, a01.y, a23.y, bb.x, bb.y);
            }
        }
        // epilogue: +b3, relu, tf32, store into sH (k-reordered for stage2 A)
        #pragma unroll
        for (int nt = 0; nt < 16; nt++) {
            int col0 = h * 128 + nt * 8 + 2 * tg;
            int cb = (h * 16 + nt) * 8;
            int p0 = kpos(2 * tg), p1 = kpos(2 * tg + 1);
            float y0 = tf32r(fmaxf(acc1[nt][0] + sb3[col0    ], 0.f));
            float y1 = tf32r(fmaxf(acc1[nt][1] + sb3[col0 + 1], 0.f));
            float y2 = tf32r(fmaxf(acc1[nt][2] + sb3[col0    ], 0.f));
            float y3 = tf32r(fmaxf(acc1[nt][3] + sb3[col0 + 1], 0.f));
            sH[(rw0 + g    ) * SHS + cb + p0] = y0;
            sH[(rw0 + g    ) * SHS + cb + p1] = y1;
            sH[(rw0 + g + 8) * SHS + cb + p0] = y2;
            sH[(rw0 + g + 8) * SHS + cb + p1] = y3;
        }
    }
    __syncthreads();

    // ================= stage 2: Y = H @ W4^T + b4 =================
    // preload W4 chunk 0 into sP0
    {
        int n = (t >> 3), q = t & 7;
        #pragma unroll
        for (int j = 0; j < 8; j++)
            st_reord4(sP0 + (j * 32 + n) * SWS, q * 4,
                      tf4(*(const float4*)(W4 + (long)(j * 32 + n) * 256 + q * 4)));
    }
    __syncthreads();

    float acc2[32][4];
    #pragma unroll
    for (int nt = 0; nt < 32; nt++)
        #pragma unroll
        for (int q = 0; q < 4; q++) acc2[nt][q] = 0.f;

    #pragma unroll 1
    for (int c = 0; c < 8; c++) {
        float* bufc = (c & 1) ? sP1 : sP0;
        float4 pre[8];
        if (c < 7) {
            int n = (t >> 3), q = t & 7;
            #pragma unroll
            for (int j = 0; j < 8; j++)
                pre[j] = tf4(*(const float4*)(W4 + (long)(j * 32 + n) * 256 + (c + 1) * 32 + q * 4));
        }
        #pragma unroll
        for (int ks = 0; ks < 4; ks++) {
            int kk = c * 32 + ks * 8;
            float2 a01 = *(const float2*)(sH + (rw0 + g) * SHS + kk + 2 * tg);
            float2 a23 = *(const float2*)(sH + (rw0 + g + 8) * SHS + kk + 2 * tg);
            #pragma unroll
            for (int nt = 0; nt < 32; nt++) {
                float2 bb = *(const float2*)(bufc + (nt * 8 + g) * SWS + ks * 8 + 2 * tg);
                mma8(acc2[nt], a01.x, a23.x, a01.y, a23.y, bb.x, bb.y);
            }
        }
        if (c < 7) {
            __syncthreads();
            float* bufn = ((c + 1) & 1) ? sP1 : sP0;
            int n = (t >> 3), q = t & 7;
            #pragma unroll
            for (int j = 0; j < 8; j++)
                st_reord4(bufn + (j * 32 + n) * SWS, q * 4, pre[j]);
            __syncthreads();
        }
    }
    __syncthreads();

    // ---- epilogue 2: +b4 into sY (=sH region), row L2 norm, coalesced store ----
    float* sY = sH;
    #pragma unroll
    for (int nt = 0; nt < 32; nt++) {
        int col0 = nt * 8 + 2 * tg;
        float y0 = acc2[nt][0] + sb4[col0];
        float y1 = acc2[nt][1] + sb4[col0 + 1];
        float y2 = acc2[nt][2] + sb4[col0];
        float y3 = acc2[nt][3] + sb4[col0 + 1];
        sY[(rw0 + g    ) * SHS + col0    ] = y0;
        sY[(rw0 + g    ) * SHS + col0 + 1] = y1;
        sY[(rw0 + g + 8) * SHS + col0    ] = y2;
        sY[(rw0 + g + 8) * SHS + col0 + 1] = y3;
    }
    __syncthreads();
    if (t < 128) {
        const float4* yr = (const float4*)(sY + (long)t * SHS);
        float s = 0.f;
        #pragma unroll 8
        for (int q = 0; q < 64; q++) {
            float4 v = yr[q];
            s += v.x * v.x + v.y * v.y + v.z * v.z + v.w * v.w;
        }
        srn[t] = 1.f / (sqrtf(s) + 1e-7f);
    }
    __syncthreads();
    #pragma unroll 2
    for (int i = t; i < 8192; i += 256) {
        int r = i >> 6, q = i & 63;
        float4 v = *(const float4*)(sY + (long)r * SHS + q * 4);
        float sc = srn[r];
        v.x *= sc; v.y *= sc; v.z *= sc; v.w *= sc;
        *(float4*)(out1 + (row0 + r) * 256 + q * 4) = v;
    }
}

// ---------------- host launcher ----------------
extern "C" void kernel_launch(void* const* d_in, const int* in_sizes, int n_in,
                              void* d_out, int out_size) {
    const float* feat0 = (const float*)d_in[0];
    const float* feat1 = (const float*)d_in[1];
    const float* W1    = (const float*)d_in[2];
    const float* b1    = (const float*)d_in[3];
    const float* gamma = (const float*)d_in[4];
    const float* beta  = (const float*)d_in[5];
    const float* W2    = (const float*)d_in[6];
    const float* b2    = (const float*)d_in[7];
    const float* W3    = (const float*)d_in[8];
    const float* b3    = (const float*)d_in[9];
    const float* W4    = (const float*)d_in[10];
    const float* b4    = (const float*)d_in[11];
    const int* patch_id0 = (const int*)d_in[12];
    const int* patch_id1 = (const int*)d_in[13];
    const int* local_id0 = (const int*)d_in[14];
    const int* local_id1 = (const int*)d_in[15];
    (void)in_sizes; (void)n_in; (void)out_size;

    float* out0 = (float*)d_out;
    float* out1 = out0 + (long)NS0 * O0;

    float* fr0; cudaGetSymbolAddress((void**)&fr0, g_fr0);
    float* fr1; cudaGetSymbolAddress((void**)&fr1, g_fr1);
    float* X0;  cudaGetSymbolAddress((void**)&X0,  g_X0);
    float* H;   cudaGetSymbolAddress((void**)&H,   g_H);
    float* Ab;  cudaGetSymbolAddress((void**)&Ab,  g_A);
    float* P;   cudaGetSymbolAddress((void**)&P,   g_P);

    int smem_mlp = SMEM_FLOATS * 4;
    cudaFuncSetAttribute(mlp_mma_kernel, cudaFuncAttributeMaxDynamicSharedMemorySize, smem_mlp);

    // transposes
    transpose_feat<<<512, 256>>>(feat0, fr0, BB, C0, HW0);
    transpose_feat<<<4096, 256>>>(feat1, fr1, BB, C1, HW1);

    // sampling
    sample0_kernel<<<NS0, 256>>>(patch_id0, local_id0);
    sample1_kernel<<<NS1, 128>>>(patch_id1, local_id1);

    // path0: gemm1 (512x1024x512, split-K 4) -> BN -> relu -> gemm2 (512x256x1024, split-K 8)
    {
        dim3 g(H1 / 64, NS0 / 64, 4);
        sgemm_sk<<<g, 256>>>(X0, W1, P, NS0, H1, C0, C0 / 4);
        reduce_bias<<<512, 256>>>(P, b1, H, NS0, H1, 4);
    }
    bnstats_kernel<<<H1, 128>>>(gamma, beta);
    bnapply_kernel<<<1024, 256>>>();
    {
        dim3 g(O0 / 64, NS0 / 64, 8);
        sgemm_sk<<<g, 256>>>(Ab, W2, P, NS0, O0, H1, H1 / 8);
        reduce_bias<<<128, 256>>>(P, b2, out0, NS0, O0, 8);
    }

    // path1: fused tf32 mma MLP
    mlp_mma_kernel<<<ROWS1 / 128, 256, smem_mlp>>>(W3, b3, W4, b4, out1);
}

// round 4
// speedup vs baseline: 2.6807x; 1.1316x over previous
#include <cuda_runtime.h>
#include <math.h>
#include <stdint.h>

// ---------------- problem constants ----------------
#define BB   8
#define C0   512
#define HW0  64
#define N0   64
#define L0   8
#define KN0  4
#define C1   64
#define HW1  16384
#define N1   512
#define L1   80
#define KN1  40
#define M1   41          // 1 center + 40
#define NS0  (BB*N0)     // 512 samples path0
#define NS1  (BB*N1)     // 4096 samples path1
#define ROWS1 (NS1*M1)   // 167936
#define H1   1024
#define O0   256
#define O1   256

// ---------------- scratch (static device arrays; no allocs) ----------------
__device__ float g_fr0[BB*HW0*C0];      // transposed feat0: (b, p, c)
__device__ float g_fr1[BB*HW1*C1];      // transposed feat1: (b, p, c)
__device__ float g_X0[NS0*C0];
__device__ float g_H [NS0*H1];
__device__ float g_A [NS0*H1];
__device__ float g_scale[H1];
__device__ float g_shift[H1];
__device__ float g_X1[(long)ROWS1*C1];  // gathered rows for path1

// ================= tf32 helpers (compute_80-level PTX only) =================
__device__ __forceinline__ float tf32r(float x) {
    uint32_t u;
    asm("cvt.rna.tf32.f32 %0, %1;" : "=r"(u) : "f"(x));
    return __uint_as_float(u);
}
__device__ __forceinline__ float4 tf4(float4 v) {
    v.x = tf32r(v.x); v.y = tf32r(v.y); v.z = tf32r(v.z); v.w = tf32r(v.w);
    return v;
}
__device__ __forceinline__ void mma8(float acc[4], float a0, float a1, float a2, float a3,
                                     float b0, float b1) {
    asm volatile(
        "mma.sync.aligned.m16n8k8.row.col.f32.tf32.tf32.f32 "
        "{%0,%1,%2,%3}, {%4,%5,%6,%7}, {%8,%9}, {%0,%1,%2,%3};"
        : "+f"(acc[0]), "+f"(acc[1]), "+f"(acc[2]), "+f"(acc[3])
        : "r"(__float_as_uint(a0)), "r"(__float_as_uint(a1)),
          "r"(__float_as_uint(a2)), "r"(__float_as_uint(a3)),
          "r"(__float_as_uint(b0)), "r"(__float_as_uint(b1)));
}
// k-pair reorder within each 8-block: col k stored at pos ((k&3)<<1)|(k>>2),
// so (k, k+4) are adjacent -> fragment loads become single lds.64.
__device__ __forceinline__ int kpos(int k) { return ((k & 3) << 1) | (k >> 2); }
__device__ __forceinline__ void st_reord4(float* rowp, int k0, float4 v) {
    rowp[((k0  ) >> 3) * 8 + kpos((k0  ) & 7)] = v.x;
    rowp[((k0+1) >> 3) * 8 + kpos((k0+1) & 7)] = v.y;
    rowp[((k0+2) >> 3) * 8 + kpos((k0+2) & 7)] = v.z;
    rowp[((k0+3) >> 3) * 8 + kpos((k0+3) & 7)] = v.w;
}

// ---------------- coalesced transposes ----------------
// feat1: (8, 64, 16384) -> (8, 16384, 64)
__global__ void transpose_feat1(const float* __restrict__ f, float* __restrict__ out) {
    __shared__ float sm[64 * 33];
    int b = blockIdx.y;
    int p0 = blockIdx.x * 32;
    int t = threadIdx.x;
    int pp = t & 31, c0 = t >> 5;
    #pragma unroll
    for (int i = 0; i < 8; i++) {
        int c = c0 + i * 8;
        sm[c * 33 + pp] = f[((long)b * 64 + c) * 16384 + p0 + pp];
    }
    __syncthreads();
    #pragma unroll
    for (int i = 0; i < 8; i++) {
        int idx = i * 256 + t;
        int p = idx >> 6, c = idx & 63;
        out[((long)b * 16384 + p0 + p) * 64 + c] = sm[c * 33 + p];
    }
}
// feat0: (8, 512, 64) -> (8, 64, 512)
__global__ void transpose_feat0(const float* __restrict__ f, float* __restrict__ out) {
    __shared__ float sm[32 * 65];
    int b = blockIdx.y;
    int c0 = blockIdx.x * 32;
    int t = threadIdx.x;
    int p = t & 63, cc = t >> 6;
    #pragma unroll
    for (int i = 0; i < 8; i++) {
        int c = cc + i * 4;
        sm[c * 65 + p] = f[((long)b * 512 + c0 + c) * 64 + p];
    }
    __syncthreads();
    #pragma unroll
    for (int i = 0; i < 8; i++) {
        int idx = i * 256 + t;
        int p2 = idx >> 5, c = idx & 31;
        out[((long)b * 64 + p2) * 512 + c0 + c] = sm[c * 65 + p2];
    }
}

// ---------------- path0 sampling ----------------
__global__ void sample0_kernel(const int* __restrict__ pid, const int* __restrict__ lid) {
    __shared__ float cen[C0];
    __shared__ float sim[L0];
    __shared__ int   rowsS[L0];
    __shared__ int   chosen[KN0];
    int blk = blockIdx.x;
    int b = blk / N0, n = blk % N0;
    int t = threadIdx.x;
    int p = pid[n];
    const float* base = g_fr0 + (long)b * HW0 * C0;
    const float* cptr = base + (long)p * C0;
    for (int c = t; c < C0; c += 256) cen[c] = cptr[c];
    if (t < L0) rowsS[t] = lid[n * L0 + t];
    __syncthreads();
    int w = t >> 5, lane = t & 31;
    {
        const float* lp = base + (long)rowsS[w] * C0;
        float dot = 0.f, ss = 0.f;
        for (int c = lane; c < C0; c += 32) {
            float v = lp[c];
            dot += v * cen[c];
            ss  += v * v;
        }
        for (int o = 16; o > 0; o >>= 1) {
            dot += __shfl_down_sync(0xffffffffu, dot, o);
            ss  += __shfl_down_sync(0xffffffffu, ss,  o);
        }
        if (lane == 0) sim[w] = dot / fmaxf(sqrtf(ss), 1e-12f);
    }
    __syncthreads();
    if (t < L0) {   // rank-based selection (jax top_k order: desc value, asc index)
        int l = t;
        float v = sim[l];
        int cnt = 0;
        #pragma unroll
        for (int j = 0; j < L0; j++) {
            float u = sim[j];
            cnt += (u > v || (u == v && j < l)) ? 1 : 0;
        }
        if (cnt < KN0) chosen[cnt] = rowsS[l];
    }
    __syncthreads();
    for (int c = t; c < C0; c += 256) {
        float acc = cen[c];
        #pragma unroll
        for (int r = 0; r < KN0; r++) acc += base[(long)chosen[r] * C0 + c];
        g_X0[(long)blk * C0 + c] = acc * 0.2f;
    }
}

// ---------------- path1 sampling ----------------
__global__ void sample1_kernel(const int* __restrict__ pid, const int* __restrict__ lid) {
    __shared__ float cen[C1];
    __shared__ float sim[L1];
    __shared__ int   rowsS[L1];
    __shared__ int   sel[KN1];
    int blk = blockIdx.x;
    int b = blk / N1, n = blk % N1;
    int t = threadIdx.x;
    const float* base = g_fr1 + (long)b * HW1 * C1;
    int p = pid[n];
    if (t < C1) cen[t] = base[(long)p * C1 + t];
    if (t < L1) rowsS[t] = lid[n * L1 + t];
    __syncthreads();
    int w = t >> 5, lane = t & 31;
    for (int l = w; l < L1; l += 4) {
        const float* lp = base + (long)rowsS[l] * C1;
        float v0 = lp[lane], v1 = lp[lane + 32];
        float dot = v0 * cen[lane] + v1 * cen[lane + 32];
        float ss  = v0 * v0 + v1 * v1;
        for (int o = 16; o > 0; o >>= 1) {
            dot += __shfl_down_sync(0xffffffffu, dot, o);
            ss  += __shfl_down_sync(0xffffffffu, ss,  o);
        }
        if (lane == 0) sim[l] = dot / fmaxf(sqrtf(ss), 1e-12f);
    }
    __syncthreads();
    if (t < L1) {   // rank-based selection
        int l = t;
        float v = sim[l];
        int cnt = 0;
        #pragma unroll
        for (int j = 0; j < L1; j++) {
            float u = sim[j];
            cnt += (u > v || (u == v && j < l)) ? 1 : 0;
        }
        if (cnt < KN1) sel[cnt] = l;
    }
    __syncthreads();
    long obase = (long)blk * M1 * C1;
    for (int idx = t; idx < M1 * C1; idx += 128) {
        int m = idx / C1, c = idx % C1;
        int src = (m == 0) ? p : rowsS[sel[m - 1]];
        g_X1[obase + idx] = base[(long)src * C1 + c];
    }
}

// ---------------- tf32 mma GEMM for path0: C[M,N] = A@Bw^T + bias ----------------
// CTA tile: 128 rows x NT cols, 256 threads; warp w owns rows 16w, nt tiles of 8 cols.
template<int NT>
__global__ __launch_bounds__(256) void gemm_tf32(const float* __restrict__ A,
                                                 const float* __restrict__ Bw,
                                                 const float* __restrict__ bias,
                                                 float* __restrict__ C,
                                                 int M, int N, int K) {
    __shared__ float sA[128 * 40];
    __shared__ float sB[NT * 40];
    int t = threadIdx.x;
    int w = t >> 5, lane = t & 31;
    int g = lane >> 2, tg = lane & 3;
    int rw0 = w * 16;
    int m0 = blockIdx.y * 128, n0 = blockIdx.x * NT;

    float acc[NT / 8][4];
    #pragma unroll
    for (int nt = 0; nt < NT / 8; nt++)
        #pragma unroll
        for (int q = 0; q < 4; q++) acc[nt][q] = 0.f;

    const float4* A4 = (const float4*)A;
    const float4* B4 = (const float4*)Bw;
    int K4 = K >> 2;

    for (int kc = 0; kc < K / 32; kc++) {
        __syncthreads();
        #pragma unroll
        for (int i = 0; i < 4; i++) {
            int idx = i * 256 + t;               // 1024 float4 = 128x32
            int r = idx >> 3, q = idx & 7;
            st_reord4(sA + r * 40, q * 4, tf4(A4[(long)(m0 + r) * K4 + kc * 8 + q]));
        }
        #pragma unroll
        for (int i = 0; i < NT / 32; i++) {
            int idx = i * 256 + t;               // NT x 32
            int r = idx >> 3, q = idx & 7;
            st_reord4(sB + r * 40, q * 4, tf4(B4[(long)(n0 + r) * K4 + kc * 8 + q]));
        }
        __syncthreads();
        #pragma unroll
        for (int ks = 0; ks < 4; ks++) {
            float2 a01 = *(const float2*)(sA + (rw0 + g) * 40 + ks * 8 + 2 * tg);
            float2 a23 = *(const float2*)(sA + (rw0 + g + 8) * 40 + ks * 8 + 2 * tg);
            #pragma unroll
            for (int nt = 0; nt < NT / 8; nt++) {
                float2 bb = *(const float2*)(sB + (nt * 8 + g) * 40 + ks * 8 + 2 * tg);
                mma8(acc[nt], a01.x, a23.x, a01.y, a23.y, bb.x, bb.y);
            }
        }
    }
    #pragma unroll
    for (int nt = 0; nt < NT / 8; nt++) {
        int col = n0 + nt * 8 + 2 * tg;
        float bj0 = bias[col], bj1 = bias[col + 1];
        C[(long)(m0 + rw0 + g    ) * N + col    ] = acc[nt][0] + bj0;
        C[(long)(m0 + rw0 + g    ) * N + col + 1] = acc[nt][1] + bj1;
        C[(long)(m0 + rw0 + g + 8) * N + col    ] = acc[nt][2] + bj0;
        C[(long)(m0 + rw0 + g + 8) * N + col + 1] = acc[nt][3] + bj1;
    }
}

// ---------------- BN ----------------
__global__ void bnstats_kernel(const float* __restrict__ gamma, const float* __restrict__ beta) {
    int j = blockIdx.x;
    int t = threadIdx.x;
    float s = 0.f, ss = 0.f;
    for (int r = t; r < NS0; r += 128) {
        float v = g_H[(long)r * H1 + j];
        s += v; ss += v * v;
    }
    __shared__ float sm[128], sm2[128];
    sm[t] = s; sm2[t] = ss;
    __syncthreads();
    for (int o = 64; o > 0; o >>= 1) {
        if (t < o) { sm[t] += sm[t + o]; sm2[t] += sm2[t + o]; }
        __syncthreads();
    }
    if (t == 0) {
        float mu  = sm[0] / NS0;
        float var = sm2[0] / NS0 - mu * mu;
        float sc  = gamma[j] / sqrtf(var + 1e-5f);
        g_scale[j] = sc;
        g_shift[j] = beta[j] - mu * sc;
    }
}

__global__ void bnapply_kernel() {
    long total = (long)NS0 * H1;
    for (long i = (long)blockIdx.x * blockDim.x + threadIdx.x; i < total;
         i += (long)gridDim.x * blockDim.x) {
        int j = (int)(i % H1);
        float v = g_H[i] * g_scale[j] + g_shift[j];
        g_A[i] = fmaxf(v, 0.f);
    }
}

// ================= fused path1 MLP via mma.sync tf32 (unchanged from R3) =================
#define SHS 264
#define SXS 72
#define SW3S 72
#define SWS 40
#define SMEM_FLOATS (33792 + 10240 + 10240 + 256 + 256 + 128)

__global__ __launch_bounds__(256, 1) void mlp_mma_kernel(const float* __restrict__ W3,
                                                         const float* __restrict__ b3,
                                                         const float* __restrict__ W4,
                                                         const float* __restrict__ b4,
                                                         float* __restrict__ out1) {
    extern __shared__ float sm[];
    float* sH  = sm;
    float* sP0 = sm + 33792;
    float* sP1 = sm + 44032;
    float* sb3 = sm + 54272;
    float* sb4 = sm + 54528;
    float* srn = sm + 54784;

    int t = threadIdx.x;
    int w = t >> 5, lane = t & 31;
    int g = lane >> 2, tg = lane & 3;
    int rw0 = w * 16;
    long row0 = (long)blockIdx.x * 128;

    sb3[t] = b3[t];
    sb4[t] = b4[t];

    {
        const float4* Xg = (const float4*)(g_X1 + row0 * 64);
        for (int i = t; i < 2048; i += 256) {
            int r = i >> 4, cq = i & 15;
            st_reord4(sP0 + r * SXS, cq * 4, tf4(Xg[i]));
        }
    }

    const float4* W3g = (const float4*)W3;
    #pragma unroll 1
    for (int h = 0; h < 2; h++) {
        __syncthreads();
        for (int i = t; i < 2048; i += 256) {
            int n = i >> 4, cq = i & 15;
            st_reord4(sP1 + n * SW3S, cq * 4, tf4(W3g[(h * 128 + n) * 16 + cq]));
        }
        __syncthreads();

        float acc1[16][4];
        #pragma unroll
        for (int nt = 0; nt < 16; nt++)
            #pragma unroll
            for (int q = 0; q < 4; q++) acc1[nt][q] = 0.f;

        #pragma unroll
        for (int ks = 0; ks < 8; ks++) {
            float2 a01 = *(const float2*)(sP0 + (rw0 + g) * SXS + ks * 8 + 2 * tg);
            float2 a23 = *(const float2*)(sP0 + (rw0 + g + 8) * SXS + ks * 8 + 2 * tg);
            #pragma unroll
            for (int nt = 0; nt < 16; nt++) {
                float2 bb = *(const float2*)(sP1 + (nt * 8 + g) * SW3S + ks * 8 + 2 * tg);
                mma8(acc1[nt], a01.x, a23.x, a01.y, a23.y, bb.x, bb.y);
            }
        }
        #pragma unroll
        for (int nt = 0; nt < 16; nt++) {
            int col0 = h * 128 + nt * 8 + 2 * tg;
            int cb = (h * 16 + nt) * 8;
            int p0 = kpos(2 * tg), p1 = kpos(2 * tg + 1);
            float y0 = tf32r(fmaxf(acc1[nt][0] + sb3[col0    ], 0.f));
            float y1 = tf32r(fmaxf(acc1[nt][1] + sb3[col0 + 1], 0.f));
            float y2 = tf32r(fmaxf(acc1[nt][2] + sb3[col0    ], 0.f));
            float y3 = tf32r(fmaxf(acc1[nt][3] + sb3[col0 + 1], 0.f));
            sH[(rw0 + g    ) * SHS + cb + p0] = y0;
            sH[(rw0 + g    ) * SHS + cb + p1] = y1;
            sH[(rw0 + g + 8) * SHS + cb + p0] = y2;
            sH[(rw0 + g + 8) * SHS + cb + p1] = y3;
        }
    }
    __syncthreads();

    {
        int n = (t >> 3), q = t & 7;
        #pragma unroll
        for (int j = 0; j < 8; j++)
            st_reord4(sP0 + (j * 32 + n) * SWS, q * 4,
                      tf4(*(const float4*)(W4 + (long)(j * 32 + n) * 256 + q * 4)));
    }
    __syncthreads();

    float acc2[32][4];
    #pragma unroll
    for (int nt = 0; nt < 32; nt++)
        #pragma unroll
        for (int q = 0; q < 4; q++) acc2[nt][q] = 0.f;

    #pragma unroll 1
    for (int c = 0; c < 8; c++) {
        float* bufc = (c & 1) ? sP1 : sP0;
        float4 pre[8];
        if (c < 7) {
            int n = (t >> 3), q = t & 7;
            #pragma unroll
            for (int j = 0; j < 8; j++)
                pre[j] = tf4(*(const float4*)(W4 + (long)(j * 32 + n) * 256 + (c + 1) * 32 + q * 4));
        }
        #pragma unroll
        for (int ks = 0; ks < 4; ks++) {
            int kk = c * 32 + ks * 8;
            float2 a01 = *(const float2*)(sH + (rw0 + g) * SHS + kk + 2 * tg);
            float2 a23 = *(const float2*)(sH + (rw0 + g + 8) * SHS + kk + 2 * tg);
            #pragma unroll
            for (int nt = 0; nt < 32; nt++) {
                float2 bb = *(const float2*)(bufc + (nt * 8 + g) * SWS + ks * 8 + 2 * tg);
                mma8(acc2[nt], a01.x, a23.x, a01.y, a23.y, bb.x, bb.y);
            }
        }
        if (c < 7) {
            __syncthreads();
            float* bufn = ((c + 1) & 1) ? sP1 : sP0;
            int n = (t >> 3), q = t & 7;
            #pragma unroll
            for (int j = 0; j < 8; j++)
                st_reord4(bufn + (j * 32 + n) * SWS, q * 4, pre[j]);
            __syncthreads();
        }
    }
    __syncthreads();

    float* sY = sH;
    #pragma unroll
    for (int nt = 0; nt < 32; nt++) {
        int col0 = nt * 8 + 2 * tg;
        float y0 = acc2[nt][0] + sb4[col0];
        float y1 = acc2[nt][1] + sb4[col0 + 1];
        float y2 = acc2[nt][2] + sb4[col0];
        float y3 = acc2[nt][3] + sb4[col0 + 1];
        sY[(rw0 + g    ) * SHS + col0    ] = y0;
        sY[(rw0 + g    ) * SHS + col0 + 1] = y1;
        sY[(rw0 + g + 8) * SHS + col0    ] = y2;
        sY[(rw0 + g + 8) * SHS + col0 + 1] = y3;
    }
    __syncthreads();
    if (t < 128) {
        const float4* yr = (const float4*)(sY + (long)t * SHS);
        float s = 0.f;
        #pragma unroll 8
        for (int q = 0; q < 64; q++) {
            float4 v = yr[q];
            s += v.x * v.x + v.y * v.y + v.z * v.z + v.w * v.w;
        }
        srn[t] = 1.f / (sqrtf(s) + 1e-7f);
    }
    __syncthreads();
    #pragma unroll 2
    for (int i = t; i < 8192; i += 256) {
        int r = i >> 6, q = i & 63;
        float4 v = *(const float4*)(sY + (long)r * SHS + q * 4);
        float sc = srn[r];
        v.x *= sc; v.y *= sc; v.z *= sc; v.w *= sc;
        *(float4*)(out1 + (row0 + r) * 256 + q * 4) = v;
    }
}

// ---------------- host launcher ----------------
extern "C" void kernel_launch(void* const* d_in, const int* in_sizes, int n_in,
                              void* d_out, int out_size) {
    const float* feat0 = (const float*)d_in[0];
    const float* feat1 = (const float*)d_in[1];
    const float* W1    = (const float*)d_in[2];
    const float* b1    = (const float*)d_in[3];
    const float* gamma = (const float*)d_in[4];
    const float* beta  = (const float*)d_in[5];
    const float* W2    = (const float*)d_in[6];
    const float* b2    = (const float*)d_in[7];
    const float* W3    = (const float*)d_in[8];
    const float* b3    = (const float*)d_in[9];
    const float* W4    = (const float*)d_in[10];
    const float* b4    = (const float*)d_in[11];
    const int* patch_id0 = (const int*)d_in[12];
    const int* patch_id1 = (const int*)d_in[13];
    const int* local_id0 = (const int*)d_in[14];
    const int* local_id1 = (const int*)d_in[15];
    (void)in_sizes; (void)n_in; (void)out_size;

    float* out0 = (float*)d_out;
    float* out1 = out0 + (long)NS0 * O0;

    float* fr0; cudaGetSymbolAddress((void**)&fr0, g_fr0);
    float* fr1; cudaGetSymbolAddress((void**)&fr1, g_fr1);
    float* X0;  cudaGetSymbolAddress((void**)&X0,  g_X0);
    float* H;   cudaGetSymbolAddress((void**)&H,   g_H);
    float* Ab;  cudaGetSymbolAddress((void**)&Ab,  g_A);

    int smem_mlp = SMEM_FLOATS * 4;
    cudaFuncSetAttribute(mlp_mma_kernel, cudaFuncAttributeMaxDynamicSharedMemorySize, smem_mlp);

    // transposes (coalesced, smem-tiled)
    {
        dim3 g1(HW1 / 32, BB);
        transpose_feat1<<<g1, 256>>>(feat1, fr1);
        dim3 g0(C0 / 32, BB);
        transpose_feat0<<<g0, 256>>>(feat0, fr0);
    }

    // sampling
    sample0_kernel<<<NS0, 256>>>(patch_id0, local_id0);
    sample1_kernel<<<NS1, 128>>>(patch_id1, local_id1);

    // path0: tf32 mma gemms
    {
        dim3 g(H1 / 64, NS0 / 128);      // 16 x 4
        gemm_tf32<64><<<g, 256>>>(X0, W1, b1, H, NS0, H1, C0);
    }
    bnstats_kernel<<<H1, 128>>>(gamma, beta);
    bnapply_kernel<<<1024, 256>>>();
    {
        dim3 g(O0 / 64, NS0 / 128);      // 4 x 4
        gemm_tf32<64><<<g, 256>>>(Ab, W2, b2, out0, NS0, O0, H1);
    }

    // path1: fused tf32 mma MLP
    mlp_mma_kernel<<<ROWS1 / 128, 256, smem_mlp>>>(W3, b3, W4, b4, out1);
}

// round 5
// speedup vs baseline: 4.4673x; 1.6665x over previous
#include <cuda_runtime.h>
#include <cuda_fp16.h>
#include <math.h>
#include <stdint.h>

// ---------------- problem constants ----------------
#define BB   8
#define C0   512
#define HW0  64
#define N0   64
#define L0   8
#define KN0  4
#define C1   64
#define HW1  16384
#define N1   512
#define L1   80
#define KN1  40
#define M1   41
#define NS0  (BB*N0)     // 512
#define NS1  (BB*N1)     // 4096
#define ROWS1 (NS1*M1)   // 167936
#define H1   1024
#define O0   256
#define O1   256

// ---------------- scratch ----------------
__device__ float  g_fr0[BB*HW0*C0];
__device__ float  g_fr1[BB*HW1*C1];
__device__ float  g_H [NS0*H1];
__device__ float  g_scale[H1];
__device__ float  g_shift[H1];
__device__ __half g_X0h[NS0*C0];
__device__ __half g_Ah [NS0*H1];
__device__ __half g_W1h[H1*C0];
__device__ __half g_W2h[O0*H1];
__device__ __half g_W3h[256*64];
__device__ __half g_W4h[256*256];
__device__ __half g_X1h[(long)ROWS1*C1];

// ---------------- fp16 mma helpers ----------------
// k-interleave within each 16-block: k -> ((k&7)>>1)*4 + ((k>>3)&1)*2 + (k&1)
// so (2t, 2t+1, 2t+8, 2t+9) occupy positions 4t..4t+3 -> one lds.64 per fragment.
__device__ __forceinline__ int reord16(int k) { return ((k & 7) >> 1) * 4 + ((k >> 3) & 1) * 2 + (k & 1); }
__device__ __forceinline__ int reordk(int k)  { return (k & ~15) + reord16(k & 15); }

__device__ __forceinline__ void mma16(float acc[4], uint32_t a0, uint32_t a1,
                                      uint32_t a2, uint32_t a3, uint32_t b0, uint32_t b1) {
    asm volatile(
        "mma.sync.aligned.m16n8k16.row.col.f32.f16.f16.f32 "
        "{%0,%1,%2,%3}, {%4,%5,%6,%7}, {%8,%9}, {%0,%1,%2,%3};"
        : "+f"(acc[0]), "+f"(acc[1]), "+f"(acc[2]), "+f"(acc[3])
        : "r"(a0), "r"(a1), "r"(a2), "r"(a3), "r"(b0), "r"(b1));
}

// ---------------- weight convert: fp32 -> fp16 with k-reorder ----------------
__global__ void cvt_reord(const float* __restrict__ src, __half* __restrict__ dst,
                          long total, int K) {
    for (long i = (long)blockIdx.x * blockDim.x + threadIdx.x; i < total;
         i += (long)gridDim.x * blockDim.x) {
        int k = (int)(i % K);
        dst[i - k + reordk(k)] = __float2half_rn(src[i]);
    }
}

// ---------------- coalesced transposes ----------------
__global__ void transpose_feat1(const float* __restrict__ f, float* __restrict__ out) {
    __shared__ float sm[64 * 33];
    int b = blockIdx.y;
    int p0 = blockIdx.x * 32;
    int t = threadIdx.x;
    int pp = t & 31, c0 = t >> 5;
    #pragma unroll
    for (int i = 0; i < 8; i++) {
        int c = c0 + i * 8;
        sm[c * 33 + pp] = f[((long)b * 64 + c) * 16384 + p0 + pp];
    }
    __syncthreads();
    #pragma unroll
    for (int i = 0; i < 8; i++) {
        int idx = i * 256 + t;
        int p = idx >> 6, c = idx & 63;
        out[((long)b * 16384 + p0 + p) * 64 + c] = sm[c * 33 + p];
    }
}
__global__ void transpose_feat0(const float* __restrict__ f, float* __restrict__ out) {
    __shared__ float sm[32 * 65];
    int b = blockIdx.y;
    int c0 = blockIdx.x * 32;
    int t = threadIdx.x;
    int p = t & 63, cc = t >> 6;
    #pragma unroll
    for (int i = 0; i < 8; i++) {
        int c = cc + i * 4;
        sm[c * 65 + p] = f[((long)b * 512 + c0 + c) * 64 + p];
    }
    __syncthreads();
    #pragma unroll
    for (int i = 0; i < 8; i++) {
        int idx = i * 256 + t;
        int p2 = idx >> 5, c = idx & 31;
        out[((long)b * 64 + p2) * 512 + c0 + c] = sm[c * 65 + p2];
    }
}

// ---------------- path0 sampling (writes half, reordered) ----------------
__global__ void sample0_kernel(const int* __restrict__ pid, const int* __restrict__ lid) {
    __shared__ float cen[C0];
    __shared__ float sim[L0];
    __shared__ int   rowsS[L0];
    __shared__ int   chosen[KN0];
    int blk = blockIdx.x;
    int b = blk / N0, n = blk % N0;
    int t = threadIdx.x;
    int p = pid[n];
    const float* base = g_fr0 + (long)b * HW0 * C0;
    const float* cptr = base + (long)p * C0;
    for (int c = t; c < C0; c += 256) cen[c] = cptr[c];
    if (t < L0) rowsS[t] = lid[n * L0 + t];
    __syncthreads();
    int w = t >> 5, lane = t & 31;
    {
        const float* lp = base + (long)rowsS[w] * C0;
        float dot = 0.f, ss = 0.f;
        for (int c = lane; c < C0; c += 32) {
            float v = lp[c];
            dot += v * cen[c];
            ss  += v * v;
        }
        for (int o = 16; o > 0; o >>= 1) {
            dot += __shfl_down_sync(0xffffffffu, dot, o);
            ss  += __shfl_down_sync(0xffffffffu, ss,  o);
        }
        if (lane == 0) sim[w] = dot / fmaxf(sqrtf(ss), 1e-12f);
    }
    __syncthreads();
    if (t < L0) {
        int l = t;
        float v = sim[l];
        int cnt = 0;
        #pragma unroll
        for (int j = 0; j < L0; j++) {
            float u = sim[j];
            cnt += (u > v || (u == v && j < l)) ? 1 : 0;
        }
        if (cnt < KN0) chosen[cnt] = rowsS[l];
    }
    __syncthreads();
    for (int c = t; c < C0; c += 256) {
        float acc = cen[c];
        #pragma unroll
        for (int r = 0; r < KN0; r++) acc += base[(long)chosen[r] * C0 + c];
        g_X0h[(long)blk * C0 + reordk(c)] = __float2half_rn(acc * 0.2f);
    }
}

// ---------------- path1 sampling (writes half, reordered) ----------------
__global__ void sample1_kernel(const int* __restrict__ pid, const int* __restrict__ lid) {
    __shared__ float cen[C1];
    __shared__ float sim[L1];
    __shared__ int   rowsS[L1];
    __shared__ int   sel[KN1];
    int blk = blockIdx.x;
    int b = blk / N1, n = blk % N1;
    int t = threadIdx.x;
    const float* base = g_fr1 + (long)b * HW1 * C1;
    int p = pid[n];
    if (t < C1) cen[t] = base[(long)p * C1 + t];
    if (t < L1) rowsS[t] = lid[n * L1 + t];
    __syncthreads();
    int w = t >> 5, lane = t & 31;
    for (int l = w; l < L1; l += 4) {
        const float* lp = base + (long)rowsS[l] * C1;
        float v0 = lp[lane], v1 = lp[lane + 32];
        float dot = v0 * cen[lane] + v1 * cen[lane + 32];
        float ss  = v0 * v0 + v1 * v1;
        for (int o = 16; o > 0; o >>= 1) {
            dot += __shfl_down_sync(0xffffffffu, dot, o);
            ss  += __shfl_down_sync(0xffffffffu, ss,  o);
        }
        if (lane == 0) sim[l] = dot / fmaxf(sqrtf(ss), 1e-12f);
    }
    __syncthreads();
    if (t < L1) {
        int l = t;
        float v = sim[l];
        int cnt = 0;
        #pragma unroll
        for (int j = 0; j < L1; j++) {
            float u = sim[j];
            cnt += (u > v || (u == v && j < l)) ? 1 : 0;
        }
        if (cnt < KN1) sel[cnt] = l;
    }
    __syncthreads();
    long obase = (long)blk * M1 * C1;
    for (int idx = t; idx < M1 * C1; idx += 128) {
        int m = idx / C1, c = idx % C1;
        int src = (m == 0) ? p : rowsS[sel[m - 1]];
        g_X1h[obase + m * C1 + reordk(c)] = __float2half_rn(base[(long)src * C1 + c]);
    }
}

// ---------------- fp16 mma GEMM (path0): C[M,N] = A@Bw^T + bias ----------------
// A, Bw pre-converted half + k-reordered. 128 rows x 64 cols per CTA, 256 threads.
__global__ __launch_bounds__(256) void gemm_fp16(const __half* __restrict__ Ah,
                                                 const __half* __restrict__ Bh,
                                                 const float* __restrict__ bias,
                                                 float* __restrict__ C,
                                                 int M, int N, int K) {
    __shared__ __half sA[128 * 48];
    __shared__ __half sB[64 * 48];
    int t = threadIdx.x;
    int w = t >> 5, lane = t & 31;
    int g = lane >> 2, tg = lane & 3;
    int rw0 = w * 16;
    int m0 = blockIdx.y * 128, n0 = blockIdx.x * 64;

    float acc[8][4];
    #pragma unroll
    for (int nt = 0; nt < 8; nt++)
        #pragma unroll
        for (int q = 0; q < 4; q++) acc[nt][q] = 0.f;

    for (int kc = 0; kc < K / 32; kc++) {
        __syncthreads();
        #pragma unroll
        for (int i = 0; i < 2; i++) {
            int idx = i * 256 + t;
            int r = idx >> 2, q = idx & 3;
            *(uint4*)(sA + r * 48 + q * 8) =
                *(const uint4*)(Ah + (long)(m0 + r) * K + kc * 32 + q * 8);
        }
        {
            int r = t >> 2, q = t & 3;
            *(uint4*)(sB + r * 48 + q * 8) =
                *(const uint4*)(Bh + (long)(n0 + r) * K + kc * 32 + q * 8);
        }
        __syncthreads();
        #pragma unroll
        for (int ks = 0; ks < 2; ks++) {
            uint2 alo = *(const uint2*)(sA + (rw0 + g) * 48 + ks * 16 + 4 * tg);
            uint2 ahi = *(const uint2*)(sA + (rw0 + g + 8) * 48 + ks * 16 + 4 * tg);
            #pragma unroll
            for (int nt = 0; nt < 8; nt++) {
                uint2 bb = *(const uint2*)(sB + (nt * 8 + g) * 48 + ks * 16 + 4 * tg);
                mma16(acc[nt], alo.x, ahi.x, alo.y, ahi.y, bb.x, bb.y);
            }
        }
    }
    #pragma unroll
    for (int nt = 0; nt < 8; nt++) {
        int col = n0 + nt * 8 + 2 * tg;
        float bj0 = bias[col], bj1 = bias[col + 1];
        C[(long)(m0 + rw0 + g    ) * N + col    ] = acc[nt][0] + bj0;
        C[(long)(m0 + rw0 + g    ) * N + col + 1] = acc[nt][1] + bj1;
        C[(long)(m0 + rw0 + g + 8) * N + col    ] = acc[nt][2] + bj0;
        C[(long)(m0 + rw0 + g + 8) * N + col + 1] = acc[nt][3] + bj1;
    }
}

// ---------------- BN ----------------
__global__ void bnstats_kernel(const float* __restrict__ gamma, const float* __restrict__ beta) {
    int j = blockIdx.x;
    int t = threadIdx.x;
    float s = 0.f, ss = 0.f;
    for (int r = t; r < NS0; r += 128) {
        float v = g_H[(long)r * H1 + j];
        s += v; ss += v * v;
    }
    __shared__ float sm[128], sm2[128];
    sm[t] = s; sm2[t] = ss;
    __syncthreads();
    for (int o = 64; o > 0; o >>= 1) {
        if (t < o) { sm[t] += sm[t + o]; sm2[t] += sm2[t + o]; }
        __syncthreads();
    }
    if (t == 0) {
        float mu  = sm[0] / NS0;
        float var = sm2[0] / NS0 - mu * mu;
        float sc  = gamma[j] / sqrtf(var + 1e-5f);
        g_scale[j] = sc;
        g_shift[j] = beta[j] - mu * sc;
    }
}

__global__ void bnapply_kernel() {
    long total = (long)NS0 * H1;
    for (long i = (long)blockIdx.x * blockDim.x + threadIdx.x; i < total;
         i += (long)gridDim.x * blockDim.x) {
        int j = (int)(i % H1);
        float v = g_H[i] * g_scale[j] + g_shift[j];
        g_Ah[i - j + reordk(j)] = __float2half_rn(fmaxf(v, 0.f));
    }
}

// ================= fused path1 MLP, fp16 mma =================
// smem (halves): sHh [0,34816) 128x272 ; phase1: sXh 34816 (128x80), sW3h 45056 (256x80)
// phase2 alias:  buf0 34816 (256x48=12288), buf1 47104 ; floats sb3/sb4 after 65536 halves.
#define MH_H   0
#define MH_X   34816
#define MH_W3  45056
#define MH_B0  34816
#define MH_B1  47104
#define MLP_SMEM_BYTES (65536*2 + 2048)

__global__ __launch_bounds__(256, 1) void mlp_fp16_kernel(const float* __restrict__ b3,
                                                          const float* __restrict__ b4,
                                                          float* __restrict__ out1) {
    extern __shared__ __half sh[];
    __half* sHh  = sh + MH_H;
    __half* sXh  = sh + MH_X;
    __half* sW3h = sh + MH_W3;
    float*  sb3  = (float*)(sh + 65536);
    float*  sb4  = sb3 + 256;

    int t = threadIdx.x;
    int w = t >> 5, lane = t & 31;
    int g = lane >> 2, tg = lane & 3;
    int rw0 = w * 16;
    long row0 = (long)blockIdx.x * 128;

    sb3[t] = b3[t];
    sb4[t] = b4[t];

    // load X tile (already half + reordered)
    #pragma unroll
    for (int i = t; i < 1024; i += 256) {
        int r = i >> 3, q = i & 7;
        *(uint4*)(sXh + r * 80 + q * 8) = *(const uint4*)(g_X1h + (row0 + r) * 64 + q * 8);
    }
    // load full W3 (256 x 64)
    #pragma unroll
    for (int i = t; i < 2048; i += 256) {
        int r = i >> 3, q = i & 7;
        *(uint4*)(sW3h + r * 80 + q * 8) = *(const uint4*)(g_W3h + (long)r * 64 + q * 8);
    }
    __syncthreads();

    // ---- stage 1: H = relu(X @ W3^T + b3), 16 rows x 256 cols per warp ----
    {
        float acc1[32][4];
        #pragma unroll
        for (int nt = 0; nt < 32; nt++)
            #pragma unroll
            for (int q = 0; q < 4; q++) acc1[nt][q] = 0.f;

        #pragma unroll
        for (int ks = 0; ks < 4; ks++) {
            uint2 alo = *(const uint2*)(sXh + (rw0 + g) * 80 + ks * 16 + 4 * tg);
            uint2 ahi = *(const uint2*)(sXh + (rw0 + g + 8) * 80 + ks * 16 + 4 * tg);
            #pragma unroll
            for (int nt = 0; nt < 32; nt++) {
                uint2 bb = *(const uint2*)(sW3h + (nt * 8 + g) * 80 + ks * 16 + 4 * tg);
                mma16(acc1[nt], alo.x, ahi.x, alo.y, ahi.y, bb.x, bb.y);
            }
        }
        #pragma unroll
        for (int nt = 0; nt < 32; nt++) {
            int col = nt * 8 + 2 * tg;
            float y0 = fmaxf(acc1[nt][0] + sb3[col    ], 0.f);
            float y1 = fmaxf(acc1[nt][1] + sb3[col + 1], 0.f);
            float y2 = fmaxf(acc1[nt][2] + sb3[col    ], 0.f);
            float y3 = fmaxf(acc1[nt][3] + sb3[col + 1], 0.f);
            int off = (nt >> 1) * 16 + 4 * tg + 2 * (nt & 1);
            *(__half2*)(sHh + (rw0 + g    ) * 272 + off) = __floats2half2_rn(y0, y1);
            *(__half2*)(sHh + (rw0 + g + 8) * 272 + off) = __floats2half2_rn(y2, y3);
        }
    }
    __syncthreads();

    // preload W4 chunk 0
    #pragma unroll
    for (int i = t; i < 1024; i += 256) {
        int r = i >> 2, q = i & 3;
        *(uint4*)(sh + MH_B0 + r * 48 + q * 8) = *(const uint4*)(g_W4h + (long)r * 256 + q * 8);
    }
    __syncthreads();

    // ---- stage 2: Y = H @ W4^T + b4 ----
    float acc2[32][4];
    #pragma unroll
    for (int nt = 0; nt < 32; nt++)
        #pragma unroll
        for (int q = 0; q < 4; q++) acc2[nt][q] = 0.f;

    #pragma unroll 1
    for (int c = 0; c < 8; c++) {
        __half* bufc = sh + ((c & 1) ? MH_B1 : MH_B0);
        uint4 pre[4];
        if (c < 7) {
            #pragma unroll
            for (int j = 0; j < 4; j++) {
                int i = j * 256 + t;
                int r = i >> 2, q = i & 3;
                pre[j] = *(const uint4*)(g_W4h + (long)r * 256 + (c + 1) * 32 + q * 8);
            }
        }
        #pragma unroll
        for (int ks = 0; ks < 2; ks++) {
            int ck = c * 2 + ks;
            uint2 alo = *(const uint2*)(sHh + (rw0 + g) * 272 + ck * 16 + 4 * tg);
            uint2 ahi = *(const uint2*)(sHh + (rw0 + g + 8) * 272 + ck * 16 + 4 * tg);
            #pragma unroll
            for (int nt = 0; nt < 32; nt++) {
                uint2 bb = *(const uint2*)(bufc + (nt * 8 + g) * 48 + ks * 16 + 4 * tg);
                mma16(acc2[nt], alo.x, ahi.x, alo.y, ahi.y, bb.x, bb.y);
            }
        }
        if (c < 7) {
            __syncthreads();
            __half* bufn = sh + (((c + 1) & 1) ? MH_B1 : MH_B0);
            #pragma unroll
            for (int j = 0; j < 4; j++) {
                int i = j * 256 + t;
                int r = i >> 2, q = i & 3;
                *(uint4*)(bufn + r * 48 + q * 8) = pre[j];
            }
            __syncthreads();
        }
    }

    // ---- epilogue: +b4, quad-shfl row sumsq, L2 norm, store ----
    float s_lo = 0.f, s_hi = 0.f;
    #pragma unroll
    for (int nt = 0; nt < 32; nt++) {
        int col = nt * 8 + 2 * tg;
        float b0 = sb4[col], b1 = sb4[col + 1];
        acc2[nt][0] += b0; acc2[nt][1] += b1;
        acc2[nt][2] += b0; acc2[nt][3] += b1;
        s_lo += acc2[nt][0] * acc2[nt][0] + acc2[nt][1] * acc2[nt][1];
        s_hi += acc2[nt][2] * acc2[nt][2] + acc2[nt][3] * acc2[nt][3];
    }
    s_lo += __shfl_xor_sync(0xffffffffu, s_lo, 1);
    s_lo += __shfl_xor_sync(0xffffffffu, s_lo, 2);
    s_hi += __shfl_xor_sync(0xffffffffu, s_hi, 1);
    s_hi += __shfl_xor_sync(0xffffffffu, s_hi, 2);
    float rn_lo = 1.f / (sqrtf(s_lo) + 1e-7f);
    float rn_hi = 1.f / (sqrtf(s_hi) + 1e-7f);

    long r_lo = row0 + rw0 + g;
    long r_hi = r_lo + 8;
    #pragma unroll
    for (int nt = 0; nt < 32; nt++) {
        int col = nt * 8 + 2 * tg;
        float2 v0 = make_float2(acc2[nt][0] * rn_lo, acc2[nt][1] * rn_lo);
        float2 v1 = make_float2(acc2[nt][2] * rn_hi, acc2[nt][3] * rn_hi);
        *(float2*)(out1 + r_lo * 256 + col) = v0;
        *(float2*)(out1 + r_hi * 256 + col) = v1;
    }
}

// ---------------- host launcher ----------------
extern "C" void kernel_launch(void* const* d_in, const int* in_sizes, int n_in,
                              void* d_out, int out_size) {
    const float* feat0 = (const float*)d_in[0];
    const float* feat1 = (const float*)d_in[1];
    const float* W1    = (const float*)d_in[2];
    const float* b1    = (const float*)d_in[3];
    const float* gamma = (const float*)d_in[4];
    const float* beta  = (const float*)d_in[5];
    const float* W2    = (const float*)d_in[6];
    const float* b2    = (const float*)d_in[7];
    const float* W3    = (const float*)d_in[8];
    const float* b3    = (const float*)d_in[9];
    const float* W4    = (const float*)d_in[10];
    const float* b4    = (const float*)d_in[11];
    const int* patch_id0 = (const int*)d_in[12];
    const int* patch_id1 = (const int*)d_in[13];
    const int* local_id0 = (const int*)d_in[14];
    const int* local_id1 = (const int*)d_in[15];
    (void)in_sizes; (void)n_in; (void)out_size;

    float* out0 = (float*)d_out;
    float* out1 = out0 + (long)NS0 * O0;

    float*  fr0; cudaGetSymbolAddress((void**)&fr0, g_fr0);
    float*  fr1; cudaGetSymbolAddress((void**)&fr1, g_fr1);
    float*  H;   cudaGetSymbolAddress((void**)&H,   g_H);
    __half* X0h; cudaGetSymbolAddress((void**)&X0h, g_X0h);
    __half* Ahp; cudaGetSymbolAddress((void**)&Ahp, g_Ah);
    __half* W1h; cudaGetSymbolAddress((void**)&W1h, g_W1h);
    __half* W2h; cudaGetSymbolAddress((void**)&W2h, g_W2h);
    __half* W3h; cudaGetSymbolAddress((void**)&W3h, g_W3h);
    __half* W4h; cudaGetSymbolAddress((void**)&W4h, g_W4h);

    cudaFuncSetAttribute(mlp_fp16_kernel, cudaFuncAttributeMaxDynamicSharedMemorySize,
                         MLP_SMEM_BYTES);

    // transposes
    {
        dim3 g1(HW1 / 32, BB);
        transpose_feat1<<<g1, 256>>>(feat1, fr1);
        dim3 g0(C0 / 32, BB);
        transpose_feat0<<<g0, 256>>>(feat0, fr0);
    }

    // weight conversions (fp32 -> fp16, k-reordered)
    cvt_reord<<<512, 256>>>(W1, W1h, (long)H1 * C0, C0);
    cvt_reord<<<256, 256>>>(W2, W2h, (long)O0 * H1, H1);
    cvt_reord<<<16,  256>>>(W3, W3h, 256L * 64, 64);
    cvt_reord<<<64,  256>>>(W4, W4h, 256L * 256, 256);

    // sampling
    sample0_kernel<<<NS0, 256>>>(patch_id0, local_id0);
    sample1_kernel<<<NS1, 128>>>(patch_id1, local_id1);

    // path0
    {
        dim3 g(H1 / 64, NS0 / 128);
        gemm_fp16<<<g, 256>>>(X0h, W1h, b1, H, NS0, H1, C0);
    }
    bnstats_kernel<<<H1, 128>>>(gamma, beta);
    bnapply_kernel<<<1024, 256>>>();
    {
        dim3 g(O0 / 64, NS0 / 128);
        gemm_fp16<<<g, 256>>>(Ahp, W2h, b2, out0, NS0, O0, H1);
    }

    // path1
    mlp_fp16_kernel<<<ROWS1 / 128, 256, MLP_SMEM_BYTES>>>(b3, b4, out1);
}

// round 6
// speedup vs baseline: 4.6393x; 1.0385x over previous
#include <cuda_runtime.h>
#include <cuda_fp16.h>
#include <math.h>
#include <stdint.h>

// ---------------- problem constants ----------------
#define BB   8
#define C0   512
#define HW0  64
#define N0   64
#define L0   8
#define KN0  4
#define C1   64
#define HW1  16384
#define N1   512
#define L1   80
#define KN1  40
#define M1   41
#define NS0  (BB*N0)     // 512
#define NS1  (BB*N1)     // 4096
#define ROWS1 (NS1*M1)   // 167936
#define H1   1024
#define O0   256
#define O1   256

// ---------------- scratch ----------------
__device__ float  g_fr0[BB*HW0*C0];
__device__ float  g_fr1[BB*HW1*C1];
__device__ float  g_H [NS0*H1];
__device__ float  g_scale[H1];
__device__ float  g_shift[H1];
__device__ float  g_bnp[2*32*H1];
__device__ __half g_X0h[NS0*C0];
__device__ __half g_Ah [NS0*H1];
__device__ __half g_W1h[H1*C0];
__device__ __half g_W2h[O0*H1];
__device__ __half g_W3h[256*64];
__device__ __half g_W4h[256*256];
__device__ __half g_X1h[(long)ROWS1*C1];

// ---------------- fp16 mma helpers ----------------
// k-interleave within each 16-block: (2t,2t+1,2t+8,2t+9) -> positions 4t..4t+3
__device__ __forceinline__ int reord16(int k) { return ((k & 7) >> 1) * 4 + ((k >> 3) & 1) * 2 + (k & 1); }
__device__ __forceinline__ int reordk(int k)  { return (k & ~15) + reord16(k & 15); }

__device__ __forceinline__ void mma16(float acc[4], uint32_t a0, uint32_t a1,
                                      uint32_t a2, uint32_t a3, uint32_t b0, uint32_t b1) {
    asm volatile(
        "mma.sync.aligned.m16n8k16.row.col.f32.f16.f16.f32 "
        "{%0,%1,%2,%3}, {%4,%5,%6,%7}, {%8,%9}, {%0,%1,%2,%3};"
        : "+f"(acc[0]), "+f"(acc[1]), "+f"(acc[2]), "+f"(acc[3])
        : "r"(a0), "r"(a1), "r"(a2), "r"(a3), "r"(b0), "r"(b1));
}

// ---------------- fused weight conversions (power-of-2 K, no divides) ----------------
#define S0E 524288L     // W1: 1024x512
#define S1E 786432L     // W2: 256x1024
#define S2E 802816L     // W3: 256x64
#define S3E 868352L     // W4: 256x256
__global__ void cvt_all(const float* __restrict__ W1, const float* __restrict__ W2,
                        const float* __restrict__ W3, const float* __restrict__ W4) {
    long i = (long)blockIdx.x * blockDim.x + threadIdx.x;
    if (i >= S3E) return;
    const float* src; __half* dst; long base; int mask;
    if (i < S0E)      { src = W1; dst = g_W1h; base = 0;   mask = 511; }
    else if (i < S1E) { src = W2; dst = g_W2h; base = S0E; mask = 1023; }
    else if (i < S2E) { src = W3; dst = g_W3h; base = S1E; mask = 63; }
    else              { src = W4; dst = g_W4h; base = S2E; mask = 255; }
    long j = i - base;
    int k = (int)j & mask;
    dst[j - k + reordk(k)] = __float2half_rn(src[j]);
}

// ---------------- coalesced transposes ----------------
__global__ void transpose_feat1(const float* __restrict__ f, float* __restrict__ out) {
    __shared__ float sm[64 * 33];
    int b = blockIdx.y;
    int p0 = blockIdx.x * 32;
    int t = threadIdx.x;
    int pp = t & 31, c0 = t >> 5;
    #pragma unroll
    for (int i = 0; i < 8; i++) {
        int c = c0 + i * 8;
        sm[c * 33 + pp] = f[((long)b * 64 + c) * 16384 + p0 + pp];
    }
    __syncthreads();
    #pragma unroll
    for (int i = 0; i < 8; i++) {
        int idx = i * 256 + t;
        int p = idx >> 6, c = idx & 63;
        out[((long)b * 16384 + p0 + p) * 64 + c] = sm[c * 33 + p];
    }
}
__global__ void transpose_feat0(const float* __restrict__ f, float* __restrict__ out) {
    __shared__ float sm[32 * 65];
    int b = blockIdx.y;
    int c0 = blockIdx.x * 32;
    int t = threadIdx.x;
    int p = t & 63, cc = t >> 6;
    #pragma unroll
    for (int i = 0; i < 8; i++) {
        int c = cc + i * 4;
        sm[c * 65 + p] = f[((long)b * 512 + c0 + c) * 64 + p];
    }
    __syncthreads();
    #pragma unroll
    for (int i = 0; i < 8; i++) {
        int idx = i * 256 + t;
        int p2 = idx >> 5, c = idx & 31;
        out[((long)b * 64 + p2) * 512 + c0 + c] = sm[c * 65 + p2];
    }
}

// ---------------- path0 sampling ----------------
__global__ void sample0_kernel(const int* __restrict__ pid, const int* __restrict__ lid) {
    __shared__ float cen[C0];
    __shared__ float sim[L0];
    __shared__ int   rowsS[L0];
    __shared__ int   chosen[KN0];
    int blk = blockIdx.x;
    int b = blk / N0, n = blk % N0;
    int t = threadIdx.x;
    int p = pid[n];
    const float* base = g_fr0 + (long)b * HW0 * C0;
    const float* cptr = base + (long)p * C0;
    for (int c = t; c < C0; c += 256) cen[c] = cptr[c];
    if (t < L0) rowsS[t] = lid[n * L0 + t];
    __syncthreads();
    int w = t >> 5, lane = t & 31;
    {
        const float* lp = base + (long)rowsS[w] * C0;
        float dot = 0.f, ss = 0.f;
        for (int c = lane; c < C0; c += 32) {
            float v = lp[c];
            dot += v * cen[c];
            ss  += v * v;
        }
        for (int o = 16; o > 0; o >>= 1) {
            dot += __shfl_down_sync(0xffffffffu, dot, o);
            ss  += __shfl_down_sync(0xffffffffu, ss,  o);
        }
        if (lane == 0) sim[w] = dot / fmaxf(sqrtf(ss), 1e-12f);
    }
    __syncthreads();
    if (t < L0) {
        int l = t;
        float v = sim[l];
        int cnt = 0;
        #pragma unroll
        for (int j = 0; j < L0; j++) {
            float u = sim[j];
            cnt += (u > v || (u == v && j < l)) ? 1 : 0;
        }
        if (cnt < KN0) chosen[cnt] = rowsS[l];
    }
    __syncthreads();
    for (int c = t; c < C0; c += 256) {
        float acc = cen[c];
        #pragma unroll
        for (int r = 0; r < KN0; r++) acc += base[(long)chosen[r] * C0 + c];
        g_X0h[(long)blk * C0 + reordk(c)] = __float2half_rn(acc * 0.2f);
    }
}

// ---------------- path1 sampling: smem-staged, thread-per-row sims ----------------
__global__ void sample1_kernel(const int* __restrict__ pid, const int* __restrict__ lid) {
    __shared__ float cen[C1];
    __shared__ float loc[L1 * 68];
    __shared__ float sim[L1];
    __shared__ int   rowsS[L1];
    __shared__ int   sel[KN1];
    int blk = blockIdx.x;
    int b = blk / N1, n = blk % N1;
    int t = threadIdx.x;
    const float* base = g_fr1 + (long)b * HW1 * C1;
    int p = pid[n];
    if (t < C1) cen[t] = base[(long)p * C1 + t];
    if (t < L1) rowsS[t] = lid[n * L1 + t];
    __syncthreads();
    // stage all 80 neighbor rows into smem (float4, conflict-free pad 68)
    #pragma unroll 2
    for (int i = t; i < L1 * 16; i += 128) {
        int l = i >> 4, c4 = i & 15;
        float4 v = *(const float4*)(base + (long)rowsS[l] * C1 + c4 * 4);
        *(float4*)(loc + l * 68 + c4 * 4) = v;
    }
    __syncthreads();
    if (t < L1) {
        const float4* lp = (const float4*)(loc + t * 68);
        const float4* cp = (const float4*)cen;
        float dot = 0.f, ss = 0.f;
        #pragma unroll
        for (int c4 = 0; c4 < 16; c4++) {
            float4 v = lp[c4], cv = cp[c4];
            dot += v.x * cv.x + v.y * cv.y + v.z * cv.z + v.w * cv.w;
            ss  += v.x * v.x + v.y * v.y + v.z * v.z + v.w * v.w;
        }
        sim[t] = dot / fmaxf(sqrtf(ss), 1e-12f);
    }
    __syncthreads();
    if (t < L1) {
        int l = t;
        float v = sim[l];
        int cnt = 0;
        #pragma unroll
        for (int j = 0; j < L1; j++) {
            float u = sim[j];
            cnt += (u > v || (u == v && j < l)) ? 1 : 0;
        }
        if (cnt < KN1) sel[cnt] = l;
    }
    __syncthreads();
    long obase = (long)blk * M1 * C1;
    #pragma unroll 2
    for (int idx = t; idx < M1 * C1; idx += 128) {
        int m = idx >> 6, c = idx & 63;
        float v = (m == 0) ? cen[c] : loc[sel[m - 1] * 68 + c];
        g_X1h[obase + m * C1 + reordk(c)] = __float2half_rn(v);
    }
}

// ---------------- fp16 mma GEMM (path0) ----------------
__global__ __launch_bounds__(256) void gemm_fp16(const __half* __restrict__ Ah,
                                                 const __half* __restrict__ Bh,
                                                 const float* __restrict__ bias,
                                                 float* __restrict__ C,
                                                 int M, int N, int K) {
    __shared__ __half sA[128 * 48];
    __shared__ __half sB[64 * 48];
    int t = threadIdx.x;
    int w = t >> 5, lane = t & 31;
    int g = lane >> 2, tg = lane & 3;
    int rw0 = w * 16;
    int m0 = blockIdx.y * 128, n0 = blockIdx.x * 64;

    float acc[8][4];
    #pragma unroll
    for (int nt = 0; nt < 8; nt++)
        #pragma unroll
        for (int q = 0; q < 4; q++) acc[nt][q] = 0.f;

    for (int kc = 0; kc < K / 32; kc++) {
        __syncthreads();
        #pragma unroll
        for (int i = 0; i < 2; i++) {
            int idx = i * 256 + t;
            int r = idx >> 2, q = idx & 3;
            *(uint4*)(sA + r * 48 + q * 8) =
                *(const uint4*)(Ah + (long)(m0 + r) * K + kc * 32 + q * 8);
        }
        {
            int r = t >> 2, q = t & 3;
            *(uint4*)(sB + r * 48 + q * 8) =
                *(const uint4*)(Bh + (long)(n0 + r) * K + kc * 32 + q * 8);
        }
        __syncthreads();
        #pragma unroll
        for (int ks = 0; ks < 2; ks++) {
            uint2 alo = *(const uint2*)(sA + (rw0 + g) * 48 + ks * 16 + 4 * tg);
            uint2 ahi = *(const uint2*)(sA + (rw0 + g + 8) * 48 + ks * 16 + 4 * tg);
            #pragma unroll
            for (int nt = 0; nt < 8; nt++) {
                uint2 bb = *(const uint2*)(sB + (nt * 8 + g) * 48 + ks * 16 + 4 * tg);
                mma16(acc[nt], alo.x, ahi.x, alo.y, ahi.y, bb.x, bb.y);
            }
        }
    }
    #pragma unroll
    for (int nt = 0; nt < 8; nt++) {
        int col = n0 + nt * 8 + 2 * tg;
        float bj0 = bias[col], bj1 = bias[col + 1];
        C[(long)(m0 + rw0 + g    ) * N + col    ] = acc[nt][0] + bj0;
        C[(long)(m0 + rw0 + g    ) * N + col + 1] = acc[nt][1] + bj1;
        C[(long)(m0 + rw0 + g + 8) * N + col    ] = acc[nt][2] + bj0;
        C[(long)(m0 + rw0 + g + 8) * N + col + 1] = acc[nt][3] + bj1;
    }
}

// ---------------- BN (two-stage, coalesced, deterministic) ----------------
__global__ void bnstatsA_kernel() {
    int b = blockIdx.x;     // 32 blocks, 16 rows each
    int t = threadIdx.x;    // 256
    float s[4] = {0.f, 0.f, 0.f, 0.f}, ss[4] = {0.f, 0.f, 0.f, 0.f};
    for (int r = 0; r < 16; r++) {
        const float* row = g_H + (long)(b * 16 + r) * H1;
        #pragma unroll
        for (int j = 0; j < 4; j++) {
            float v = row[t + 256 * j];
            s[j] += v; ss[j] += v * v;
        }
    }
    #pragma unroll
    for (int j = 0; j < 4; j++) {
        g_bnp[b * H1 + t + 256 * j] = s[j];
        g_bnp[32 * H1 + b * H1 + t + 256 * j] = ss[j];
    }
}
__global__ void bnstatsB_kernel(const float* __restrict__ gamma, const float* __restrict__ beta) {
    int j = blockIdx.x * 256 + threadIdx.x;
    float s = 0.f, ss = 0.f;
    for (int b = 0; b < 32; b++) {
        s  += g_bnp[b * H1 + j];
        ss += g_bnp[32 * H1 + b * H1 + j];
    }
    float mu  = s / NS0;
    float var = ss / NS0 - mu * mu;
    float sc  = gamma[j] / sqrtf(var + 1e-5f);
    g_scale[j] = sc;
    g_shift[j] = beta[j] - mu * sc;
}
__global__ void bnapply_kernel() {
    long total = (long)NS0 * H1;
    for (long i = (long)blockIdx.x * blockDim.x + threadIdx.x; i < total;
         i += (long)gridDim.x * blockDim.x) {
        int j = (int)(i % H1);
        float v = g_H[i] * g_scale[j] + g_shift[j];
        g_Ah[i - j + reordk(j)] = __float2half_rn(fmaxf(v, 0.f));
    }
}

// ================= fused path1 MLP, fp16 mma, 2m x 4n warp tiling =================
// smem halves: sHh[0,34816)=128x272 ; sXh 34816 (128x80); sW3 45056 (256x80) ends 65536
// buf0 65536 (256x48), buf1 77824 ; floats at half-offset 90112: b3,b4,partial[512],srn[128]
#define MH_X   34816
#define MH_W3  45056
#define MH_B0  65536
#define MH_B1  77824
#define MH_F   90112
#define MLP_SMEM_BYTES (MH_F*2 + (256+256+512+128)*4)

__global__ __launch_bounds__(256, 1) void mlp_fp16_kernel(const float* __restrict__ b3,
                                                          const float* __restrict__ b4,
                                                          float* __restrict__ out1) {
    extern __shared__ __half sh[];
    __half* sHh = sh;
    __half* sXh = sh + MH_X;
    __half* sW3 = sh + MH_W3;
    float*  sb3   = (float*)(sh + MH_F);
    float*  sb4   = sb3 + 256;
    float*  spart = sb4 + 256;      // [128][4]
    float*  srn   = spart + 512;    // [128]

    int t = threadIdx.x;
    int w = t >> 5, lane = t & 31;
    int g = lane >> 2, tg = lane & 3;
    int wm = w >> 2, wn = w & 3;
    int rbase = wm * 64, cbase = wn * 64;
    long row0 = (long)blockIdx.x * 128;

    sb3[t] = b3[t];
    sb4[t] = b4[t];

    // load X (128x64 halves) and W3 (256x64)
    #pragma unroll
    for (int i = t; i < 1024; i += 256) {
        int r = i >> 3, q = i & 7;
        *(uint4*)(sXh + r * 80 + q * 8) = *(const uint4*)(g_X1h + (row0 + r) * 64 + q * 8);
    }
    #pragma unroll
    for (int i = t; i < 2048; i += 256) {
        int r = i >> 3, q = i & 7;
        *(uint4*)(sW3 + r * 80 + q * 8) = *(const uint4*)(g_W3h + (long)r * 64 + q * 8);
    }
    __syncthreads();

    // ---- stage 1: H = relu(X @ W3^T + b3); warp tile 64 rows x 64 cols ----
    {
        float acc1[4][8][4];
        #pragma unroll
        for (int mt = 0; mt < 4; mt++)
            #pragma unroll
            for (int nt = 0; nt < 8; nt++)
                #pragma unroll
                for (int q = 0; q < 4; q++) acc1[mt][nt][q] = 0.f;

        #pragma unroll
        for (int ks = 0; ks < 4; ks++) {
            uint2 al[4], ah[4];
            #pragma unroll
            for (int mt = 0; mt < 4; mt++) {
                al[mt] = *(const uint2*)(sXh + (rbase + mt * 16 + g) * 80 + ks * 16 + 4 * tg);
                ah[mt] = *(const uint2*)(sXh + (rbase + mt * 16 + g + 8) * 80 + ks * 16 + 4 * tg);
            }
            #pragma unroll
            for (int nt = 0; nt < 8; nt++) {
                uint2 bb = *(const uint2*)(sW3 + (cbase + nt * 8 + g) * 80 + ks * 16 + 4 * tg);
                #pragma unroll
                for (int mt = 0; mt < 4; mt++)
                    mma16(acc1[mt][nt], al[mt].x, ah[mt].x, al[mt].y, ah[mt].y, bb.x, bb.y);
            }
        }
        #pragma unroll
        for (int mt = 0; mt < 4; mt++)
            #pragma unroll
            for (int nt = 0; nt < 8; nt++) {
                int col = cbase + nt * 8 + 2 * tg;
                float y0 = fmaxf(acc1[mt][nt][0] + sb3[col    ], 0.f);
                float y1 = fmaxf(acc1[mt][nt][1] + sb3[col + 1], 0.f);
                float y2 = fmaxf(acc1[mt][nt][2] + sb3[col    ], 0.f);
                float y3 = fmaxf(acc1[mt][nt][3] + sb3[col + 1], 0.f);
                int off = (wn * 4 + (nt >> 1)) * 16 + 4 * tg + 2 * (nt & 1);
                *(__half2*)(sHh + (rbase + mt * 16 + g    ) * 272 + off) = __floats2half2_rn(y0, y1);
                *(__half2*)(sHh + (rbase + mt * 16 + g + 8) * 272 + off) = __floats2half2_rn(y2, y3);
            }
    }
    __syncthreads();

    // preload W4 chunk 0
    #pragma unroll
    for (int j = 0; j < 4; j++) {
        int i = j * 256 + t;
        int r = i >> 2, q = i & 3;
        *(uint4*)(sh + MH_B0 + r * 48 + q * 8) = *(const uint4*)(g_W4h + (long)r * 256 + q * 8);
    }
    __syncthreads();

    // ---- stage 2: Y = H @ W4^T ----
    float acc2[4][8][4];
    #pragma unroll
    for (int mt = 0; mt < 4; mt++)
        #pragma unroll
        for (int nt = 0; nt < 8; nt++)
            #pragma unroll
            for (int q = 0; q < 4; q++) acc2[mt][nt][q] = 0.f;

    #pragma unroll 1
    for (int c = 0; c < 8; c++) {
        __half* bufc = sh + ((c & 1) ? MH_B1 : MH_B0);
        uint4 pre[4];
        if (c < 7) {
            #pragma unroll
            for (int j = 0; j < 4; j++) {
                int i = j * 256 + t;
                int r = i >> 2, q = i & 3;
                pre[j] = *(const uint4*)(g_W4h + (long)r * 256 + (c + 1) * 32 + q * 8);
            }
        }
        #pragma unroll
        for (int ks = 0; ks < 2; ks++) {
            int ck = c * 2 + ks;
            uint2 al[4], ah[4];
            #pragma unroll
            for (int mt = 0; mt < 4; mt++) {
                al[mt] = *(const uint2*)(sHh + (rbase + mt * 16 + g) * 272 + ck * 16 + 4 * tg);
                ah[mt] = *(const uint2*)(sHh + (rbase + mt * 16 + g + 8) * 272 + ck * 16 + 4 * tg);
            }
            #pragma unroll
            for (int nt = 0; nt < 8; nt++) {
                uint2 bb = *(const uint2*)(bufc + (cbase + nt * 8 + g) * 48 + ks * 16 + 4 * tg);
                #pragma unroll
                for (int mt = 0; mt < 4; mt++)
                    mma16(acc2[mt][nt], al[mt].x, ah[mt].x, al[mt].y, ah[mt].y, bb.x, bb.y);
            }
        }
        if (c < 7) {
            __syncthreads();
            __half* bufn = sh + (((c + 1) & 1) ? MH_B1 : MH_B0);
            #pragma unroll
            for (int j = 0; j < 4; j++) {
                int i = j * 256 + t;
                int r = i >> 2, q = i & 3;
                *(uint4*)(bufn + r * 48 + q * 8) = pre[j];
            }
            __syncthreads();
        }
    }

    // ---- epilogue: +b4, cross-warp row sumsq, L2 norm, store ----
    float slo[4] = {0.f, 0.f, 0.f, 0.f}, shi[4] = {0.f, 0.f, 0.f, 0.f};
    #pragma unroll
    for (int mt = 0; mt < 4; mt++)
        #pragma unroll
        for (int nt = 0; nt < 8; nt++) {
            int col = cbase + nt * 8 + 2 * tg;
            float b0 = sb4[col], b1 = sb4[col + 1];
            acc2[mt][nt][0] += b0; acc2[mt][nt][1] += b1;
            acc2[mt][nt][2] += b0; acc2[mt][nt][3] += b1;
            slo[mt] += acc2[mt][nt][0] * acc2[mt][nt][0] + acc2[mt][nt][1] * acc2[mt][nt][1];
            shi[mt] += acc2[mt][nt][2] * acc2[mt][nt][2] + acc2[mt][nt][3] * acc2[mt][nt][3];
        }
    #pragma unroll
    for (int mt = 0; mt < 4; mt++) {
        slo[mt] += __shfl_xor_sync(0xffffffffu, slo[mt], 1);
        slo[mt] += __shfl_xor_sync(0xffffffffu, slo[mt], 2);
        shi[mt] += __shfl_xor_sync(0xffffffffu, shi[mt], 1);
        shi[mt] += __shfl_xor_sync(0xffffffffu, shi[mt], 2);
    }
    if (tg == 0) {
        #pragma unroll
        for (int mt = 0; mt < 4; mt++) {
            spart[(rbase + mt * 16 + g) * 4 + wn]     = slo[mt];
            spart[(rbase + mt * 16 + g + 8) * 4 + wn] = shi[mt];
        }
    }
    __syncthreads();
    if (t < 128) {
        float s = spart[t * 4] + spart[t * 4 + 1] + spart[t * 4 + 2] + spart[t * 4 + 3];
        srn[t] = 1.f / (sqrtf(s) + 1e-7f);
    }
    __syncthreads();
    #pragma unroll
    for (int mt = 0; mt < 4; mt++) {
        float rlo = srn[rbase + mt * 16 + g];
        float rhi = srn[rbase + mt * 16 + g + 8];
        long glo = row0 + rbase + mt * 16 + g;
        long ghi = glo + 8;
        #pragma unroll
        for (int nt = 0; nt < 8; nt++) {
            int col = cbase + nt * 8 + 2 * tg;
            *(float2*)(out1 + glo * 256 + col) =
                make_float2(acc2[mt][nt][0] * rlo, acc2[mt][nt][1] * rlo);
            *(float2*)(out1 + ghi * 256 + col) =
                make_float2(acc2[mt][nt][2] * rhi, acc2[mt][nt][3] * rhi);
        }
    }
}

// ---------------- host launcher ----------------
extern "C" void kernel_launch(void* const* d_in, const int* in_sizes, int n_in,
                              void* d_out, int out_size) {
    const float* feat0 = (const float*)d_in[0];
    const float* feat1 = (const float*)d_in[1];
    const float* W1    = (const float*)d_in[2];
    const float* b1    = (const float*)d_in[3];
    const float* gamma = (const float*)d_in[4];
    const float* beta  = (const float*)d_in[5];
    const float* W2    = (const float*)d_in[6];
    const float* b2    = (const float*)d_in[7];
    const float* W3    = (const float*)d_in[8];
    const float* b3    = (const float*)d_in[9];
    const float* W4    = (const float*)d_in[10];
    const float* b4    = (const float*)d_in[11];
    const int* patch_id0 = (const int*)d_in[12];
    const int* patch_id1 = (const int*)d_in[13];
    const int* local_id0 = (const int*)d_in[14];
    const int* local_id1 = (const int*)d_in[15];
    (void)in_sizes; (void)n_in; (void)out_size;

    float* out0 = (float*)d_out;
    float* out1 = out0 + (long)NS0 * O0;

    float*  fr0; cudaGetSymbolAddress((void**)&fr0, g_fr0);
    float*  fr1; cudaGetSymbolAddress((void**)&fr1, g_fr1);
    float*  H;   cudaGetSymbolAddress((void**)&H,   g_H);
    __half* X0h; cudaGetSymbolAddress((void**)&X0h, g_X0h);
    __half* Ahp; cudaGetSymbolAddress((void**)&Ahp, g_Ah);
    __half* W1h; cudaGetSymbolAddress((void**)&W1h, g_W1h);
    __half* W2h; cudaGetSymbolAddress((void**)&W2h, g_W2h);

    cudaFuncSetAttribute(mlp_fp16_kernel, cudaFuncAttributeMaxDynamicSharedMemorySize,
                         MLP_SMEM_BYTES);

    // transposes
    {
        dim3 g1(HW1 / 32, BB);
        transpose_feat1<<<g1, 256>>>(feat1, fr1);
        dim3 g0(C0 / 32, BB);
        transpose_feat0<<<g0, 256>>>(feat0, fr0);
    }

    // fused weight conversion (848 blocks x 1024 = exactly S3E)
    cvt_all<<<848, 1024>>>(W1, W2, W3, W4);

    // sampling
    sample0_kernel<<<NS0, 256>>>(patch_id0, local_id0);
    sample1_kernel<<<NS1, 128>>>(patch_id1, local_id1);

    // path0
    {
        dim3 g(H1 / 64, NS0 / 128);
        gemm_fp16<<<g, 256>>>(X0h, W1h, b1, H, NS0, H1, C0);
    }
    bnstatsA_kernel<<<32, 256>>>();
    bnstatsB_kernel<<<4, 256>>>(gamma, beta);
    bnapply_kernel<<<1024, 256>>>();
    {
        dim3 g(O0 / 64, NS0 / 128);
        gemm_fp16<<<g, 256>>>(Ahp, W2h, b2, out0, NS0, O0, H1);
    }

    // path1
    mlp_fp16_kernel<<<ROWS1 / 128, 256, MLP_SMEM_BYTES>>>(b3, b4, out1);
}

// round 7
// speedup vs baseline: 5.4155x; 1.1673x over previous
#include <cuda_runtime.h>
#include <cuda_fp16.h>
#include <math.h>
#include <stdint.h>

// ---------------- problem constants ----------------
#define BB   8
#define C0   512
#define HW0  64
#define N0   64
#define L0   8
#define KN0  4
#define C1   64
#define HW1  16384
#define N1   512
#define L1   80
#define KN1  40
#define M1   41
#define NS0  (BB*N0)     // 512
#define NS1  (BB*N1)     // 4096
#define ROWS1 (NS1*M1)   // 167936
#define H1   1024
#define O0   256
#define O1   256

// ---------------- scratch ----------------
__device__ float  g_fr0[BB*HW0*C0];
__device__ float  g_fr1[BB*HW1*C1];
__device__ float  g_H [NS0*H1];
__device__ float  g_scale[H1];
__device__ float  g_shift[H1];
__device__ float  g_bnp[2*32*H1];
__device__ __half g_X0h[NS0*C0];
__device__ __half g_Ah [NS0*H1];
__device__ __half g_W1h[H1*C0];
__device__ __half g_W2h[O0*H1];
__device__ __half g_W3h[256*64];
__device__ __half g_W4h[256*256];
__device__ __half g_X1h[(long)ROWS1*C1];

// ---------------- fp16 mma helpers ----------------
__device__ __forceinline__ int reord16(int k) { return ((k & 7) >> 1) * 4 + ((k >> 3) & 1) * 2 + (k & 1); }
__device__ __forceinline__ int reordk(int k)  { return (k & ~15) + reord16(k & 15); }

__device__ __forceinline__ void mma16(float acc[4], uint32_t a0, uint32_t a1,
                                      uint32_t a2, uint32_t a3, uint32_t b0, uint32_t b1) {
    asm volatile(
        "mma.sync.aligned.m16n8k16.row.col.f32.f16.f16.f32 "
        "{%0,%1,%2,%3}, {%4,%5,%6,%7}, {%8,%9}, {%0,%1,%2,%3};"
        : "+f"(acc[0]), "+f"(acc[1]), "+f"(acc[2]), "+f"(acc[3])
        : "r"(a0), "r"(a1), "r"(a2), "r"(a3), "r"(b0), "r"(b1));
}
__device__ __forceinline__ uint32_t pack2(float a, float b) {
    __half2 h = __floats2half2_rn(a, b);
    return *(uint32_t*)&h;
}
__device__ __forceinline__ void cp16(uint32_t dst, const void* src) {
    asm volatile("cp.async.cg.shared.global [%0], [%1], 16;" :: "r"(dst), "l"(src));
}

// ---------------- fused weight conversions ----------------
#define S0E 524288L
#define S1E 786432L
#define S2E 802816L
#define S3E 868352L
__global__ void cvt_all(const float* __restrict__ W1, const float* __restrict__ W2,
                        const float* __restrict__ W3, const float* __restrict__ W4) {
    long i = (long)blockIdx.x * blockDim.x + threadIdx.x;
    if (i >= S3E) return;
    const float* src; __half* dst; long base; int mask;
    if (i < S0E)      { src = W1; dst = g_W1h; base = 0;   mask = 511; }
    else if (i < S1E) { src = W2; dst = g_W2h; base = S0E; mask = 1023; }
    else if (i < S2E) { src = W3; dst = g_W3h; base = S1E; mask = 63; }
    else              { src = W4; dst = g_W4h; base = S2E; mask = 255; }
    long j = i - base;
    int k = (int)j & mask;
    dst[j - k + reordk(k)] = __float2half_rn(src[j]);
}

// ---------------- coalesced transposes ----------------
__global__ void transpose_feat1(const float* __restrict__ f, float* __restrict__ out) {
    __shared__ float sm[64 * 33];
    int b = blockIdx.y;
    int p0 = blockIdx.x * 32;
    int t = threadIdx.x;
    int pp = t & 31, c0 = t >> 5;
    #pragma unroll
    for (int i = 0; i < 8; i++) {
        int c = c0 + i * 8;
        sm[c * 33 + pp] = f[((long)b * 64 + c) * 16384 + p0 + pp];
    }
    __syncthreads();
    #pragma unroll
    for (int i = 0; i < 8; i++) {
        int idx = i * 256 + t;
        int p = idx >> 6, c = idx & 63;
        out[((long)b * 16384 + p0 + p) * 64 + c] = sm[c * 33 + p];
    }
}
__global__ void transpose_feat0(const float* __restrict__ f, float* __restrict__ out) {
    __shared__ float sm[32 * 65];
    int b = blockIdx.y;
    int c0 = blockIdx.x * 32;
    int t = threadIdx.x;
    int p = t & 63, cc = t >> 6;
    #pragma unroll
    for (int i = 0; i < 8; i++) {
        int c = cc + i * 4;
        sm[c * 65 + p] = f[((long)b * 512 + c0 + c) * 64 + p];
    }
    __syncthreads();
    #pragma unroll
    for (int i = 0; i < 8; i++) {
        int idx = i * 256 + t;
        int p2 = idx >> 5, c = idx & 31;
        out[((long)b * 64 + p2) * 512 + c0 + c] = sm[c * 65 + p2];
    }
}

// ---------------- path0 sampling ----------------
__global__ void sample0_kernel(const int* __restrict__ pid, const int* __restrict__ lid) {
    __shared__ float cen[C0];
    __shared__ float sim[L0];
    __shared__ int   rowsS[L0];
    __shared__ int   chosen[KN0];
    int blk = blockIdx.x;
    int b = blk / N0, n = blk % N0;
    int t = threadIdx.x;
    int p = pid[n];
    const float* base = g_fr0 + (long)b * HW0 * C0;
    const float* cptr = base + (long)p * C0;
    for (int c = t; c < C0; c += 256) cen[c] = cptr[c];
    if (t < L0) rowsS[t] = lid[n * L0 + t];
    __syncthreads();
    int w = t >> 5, lane = t & 31;
    {
        const float* lp = base + (long)rowsS[w] * C0;
        float dot = 0.f, ss = 0.f;
        for (int c = lane; c < C0; c += 32) {
            float v = lp[c];
            dot += v * cen[c];
            ss  += v * v;
        }
        for (int o = 16; o > 0; o >>= 1) {
            dot += __shfl_down_sync(0xffffffffu, dot, o);
            ss  += __shfl_down_sync(0xffffffffu, ss,  o);
        }
        if (lane == 0) sim[w] = dot / fmaxf(sqrtf(ss), 1e-12f);
    }
    __syncthreads();
    if (t < L0) {
        int l = t;
        float v = sim[l];
        int cnt = 0;
        #pragma unroll
        for (int j = 0; j < L0; j++) {
            float u = sim[j];
            cnt += (u > v || (u == v && j < l)) ? 1 : 0;
        }
        if (cnt < KN0) chosen[cnt] = rowsS[l];
    }
    __syncthreads();
    for (int c = t; c < C0; c += 256) {
        float acc = cen[c];
        #pragma unroll
        for (int r = 0; r < KN0; r++) acc += base[(long)chosen[r] * C0 + c];
        g_X0h[(long)blk * C0 + reordk(c)] = __float2half_rn(acc * 0.2f);
    }
}

// ---------------- path1 sampling ----------------
__global__ void sample1_kernel(const int* __restrict__ pid, const int* __restrict__ lid) {
    __shared__ float cen[C1];
    __shared__ float loc[L1 * 68];
    __shared__ float sim[L1];
    __shared__ int   rowsS[L1];
    __shared__ int   sel[KN1];
    int blk = blockIdx.x;
    int b = blk / N1, n = blk % N1;
    int t = threadIdx.x;
    const float* base = g_fr1 + (long)b * HW1 * C1;
    int p = pid[n];
    if (t < C1) cen[t] = base[(long)p * C1 + t];
    if (t < L1) rowsS[t] = lid[n * L1 + t];
    __syncthreads();
    #pragma unroll 2
    for (int i = t; i < L1 * 16; i += 128) {
        int l = i >> 4, c4 = i & 15;
        float4 v = *(const float4*)(base + (long)rowsS[l] * C1 + c4 * 4);
        *(float4*)(loc + l * 68 + c4 * 4) = v;
    }
    __syncthreads();
    if (t < L1) {
        const float4* lp = (const float4*)(loc + t * 68);
        const float4* cp = (const float4*)cen;
        float dot = 0.f, ss = 0.f;
        #pragma unroll
        for (int c4 = 0; c4 < 16; c4++) {
            float4 v = lp[c4], cv = cp[c4];
            dot += v.x * cv.x + v.y * cv.y + v.z * cv.z + v.w * cv.w;
            ss  += v.x * v.x + v.y * v.y + v.z * v.z + v.w * v.w;
        }
        sim[t] = dot / fmaxf(sqrtf(ss), 1e-12f);
    }
    __syncthreads();
    if (t < L1) {
        int l = t;
        float v = sim[l];
        int cnt = 0;
        #pragma unroll
        for (int j = 0; j < L1; j++) {
            float u = sim[j];
            cnt += (u > v || (u == v && j < l)) ? 1 : 0;
        }
        if (cnt < KN1) sel[cnt] = l;
    }
    __syncthreads();
    long obase = (long)blk * M1 * C1;
    #pragma unroll 2
    for (int idx = t; idx < M1 * C1; idx += 128) {
        int m = idx >> 6, c = idx & 63;
        float v = (m == 0) ? cen[c] : loc[sel[m - 1] * 68 + c];
        g_X1h[obase + m * C1 + reordk(c)] = __float2half_rn(v);
    }
}

// ---------------- fp16 mma GEMM (path0) ----------------
__global__ __launch_bounds__(256) void gemm_fp16(const __half* __restrict__ Ah,
                                                 const __half* __restrict__ Bh,
                                                 const float* __restrict__ bias,
                                                 float* __restrict__ C,
                                                 int M, int N, int K) {
    __shared__ __half sA[128 * 48];
    __shared__ __half sB[64 * 48];
    int t = threadIdx.x;
    int w = t >> 5, lane = t & 31;
    int g = lane >> 2, tg = lane & 3;
    int rw0 = w * 16;
    int m0 = blockIdx.y * 128, n0 = blockIdx.x * 64;

    float acc[8][4];
    #pragma unroll
    for (int nt = 0; nt < 8; nt++)
        #pragma unroll
        for (int q = 0; q < 4; q++) acc[nt][q] = 0.f;

    for (int kc = 0; kc < K / 32; kc++) {
        __syncthreads();
        #pragma unroll
        for (int i = 0; i < 2; i++) {
            int idx = i * 256 + t;
            int r = idx >> 2, q = idx & 3;
            *(uint4*)(sA + r * 48 + q * 8) =
                *(const uint4*)(Ah + (long)(m0 + r) * K + kc * 32 + q * 8);
        }
        {
            int r = t >> 2, q = t & 3;
            *(uint4*)(sB + r * 48 + q * 8) =
                *(const uint4*)(Bh + (long)(n0 + r) * K + kc * 32 + q * 8);
        }
        __syncthreads();
        #pragma unroll
        for (int ks = 0; ks < 2; ks++) {
            uint2 alo = *(const uint2*)(sA + (rw0 + g) * 48 + ks * 16 + 4 * tg);
            uint2 ahi = *(const uint2*)(sA + (rw0 + g + 8) * 48 + ks * 16 + 4 * tg);
            #pragma unroll
            for (int nt = 0; nt < 8; nt++) {
                uint2 bb = *(const uint2*)(sB + (nt * 8 + g) * 48 + ks * 16 + 4 * tg);
                mma16(acc[nt], alo.x, ahi.x, alo.y, ahi.y, bb.x, bb.y);
            }
        }
    }
    #pragma unroll
    for (int nt = 0; nt < 8; nt++) {
        int col = n0 + nt * 8 + 2 * tg;
        float bj0 = bias[col], bj1 = bias[col + 1];
        C[(long)(m0 + rw0 + g    ) * N + col    ] = acc[nt][0] + bj0;
        C[(long)(m0 + rw0 + g    ) * N + col + 1] = acc[nt][1] + bj1;
        C[(long)(m0 + rw0 + g + 8) * N + col    ] = acc[nt][2] + bj0;
        C[(long)(m0 + rw0 + g + 8) * N + col + 1] = acc[nt][3] + bj1;
    }
}

// ---------------- BN ----------------
__global__ void bnstatsA_kernel() {
    int b = blockIdx.x;
    int t = threadIdx.x;
    float s[4] = {0.f, 0.f, 0.f, 0.f}, ss[4] = {0.f, 0.f, 0.f, 0.f};
    for (int r = 0; r < 16; r++) {
        const float* row = g_H + (long)(b * 16 + r) * H1;
        #pragma unroll
        for (int j = 0; j < 4; j++) {
            float v = row[t + 256 * j];
            s[j] += v; ss[j] += v * v;
        }
    }
    #pragma unroll
    for (int j = 0; j < 4; j++) {
        g_bnp[b * H1 + t + 256 * j] = s[j];
        g_bnp[32 * H1 + b * H1 + t + 256 * j] = ss[j];
    }
}
__global__ void bnstatsB_kernel(const float* __restrict__ gamma, const float* __restrict__ beta) {
    int j = blockIdx.x * 256 + threadIdx.x;
    float s = 0.f, ss = 0.f;
    for (int b = 0; b < 32; b++) {
        s  += g_bnp[b * H1 + j];
        ss += g_bnp[32 * H1 + b * H1 + j];
    }
    float mu  = s / NS0;
    float var = ss / NS0 - mu * mu;
    float sc  = gamma[j] / sqrtf(var + 1e-5f);
    g_scale[j] = sc;
    g_shift[j] = beta[j] - mu * sc;
}
__global__ void bnapply_kernel() {
    long total = (long)NS0 * H1;
    for (long i = (long)blockIdx.x * blockDim.x + threadIdx.x; i < total;
         i += (long)gridDim.x * blockDim.x) {
        int j = (int)(i % H1);
        float v = g_H[i] * g_scale[j] + g_shift[j];
        g_Ah[i - j + reordk(j)] = __float2half_rn(fmaxf(v, 0.f));
    }
}

// ================= path1 MLP: register-fused back-to-back fp16 mma =================
// smem halves: sX [0,10240) 128x80 ; sW3 [10240,30720) 256x80 ; sW4 [30720,100352) 256x272
// floats at half-offset 100352: sb3[256], sb4[256]
#define MH_W3  10240
#define MH_W4  30720
#define MH_F   100352
#define MLP_SMEM_BYTES (MH_F*2 + 512*4)

__global__ __launch_bounds__(256, 1) void mlp_fp16_kernel(const float* __restrict__ b3,
                                                          const float* __restrict__ b4,
                                                          float* __restrict__ out1) {
    extern __shared__ __half sh[];
    __half* sX  = sh;
    __half* sW3 = sh + MH_W3;
    __half* sW4 = sh + MH_W4;
    float*  sb3 = (float*)(sh + MH_F);
    float*  sb4 = sb3 + 256;

    int t = threadIdx.x;
    int w = t >> 5, lane = t & 31;
    int g = lane >> 2, tg = lane & 3;
    int rw0 = w * 16;
    long row0 = (long)blockIdx.x * 128;

    uint32_t sbase = (uint32_t)__cvta_generic_to_shared(sh);

    // group A: X (1024 x 16B) + W3 (2048 x 16B)
    #pragma unroll
    for (int i = t; i < 1024; i += 256) {
        int r = i >> 3, q = i & 7;
        cp16(sbase + (uint32_t)(r * 80 + q * 8) * 2, g_X1h + (row0 + r) * 64 + q * 8);
    }
    #pragma unroll
    for (int i = t; i < 2048; i += 256) {
        int r = i >> 3, q = i & 7;
        cp16(sbase + (uint32_t)(MH_W3 + r * 80 + q * 8) * 2, g_W3h + (long)r * 64 + q * 8);
    }
    asm volatile("cp.async.commit_group;" ::: "memory");
    // group B: W4 (8192 x 16B)
    #pragma unroll 4
    for (int i = t; i < 8192; i += 256) {
        int r = i >> 5, q = i & 31;
        cp16(sbase + (uint32_t)(MH_W4 + r * 272 + q * 8) * 2, g_W4h + (long)r * 256 + q * 8);
    }
    asm volatile("cp.async.commit_group;" ::: "memory");

    sb3[t] = b3[t];
    sb4[t] = b4[t];

    asm volatile("cp.async.wait_group 1;" ::: "memory");
    __syncthreads();

    // ---- stage 1: H = relu(X @ W3^T + b3); warp = 16 rows x all 256 cols ----
    float acc1[32][4];
    #pragma unroll
    for (int nt = 0; nt < 32; nt++)
        #pragma unroll
        for (int q = 0; q < 4; q++) acc1[nt][q] = 0.f;

    #pragma unroll
    for (int ks = 0; ks < 4; ks++) {
        uint2 alo = *(const uint2*)(sX + (rw0 + g) * 80 + ks * 16 + 4 * tg);
        uint2 ahi = *(const uint2*)(sX + (rw0 + g + 8) * 80 + ks * 16 + 4 * tg);
        #pragma unroll
        for (int nt = 0; nt < 32; nt++) {
            uint2 bb = *(const uint2*)(sW3 + (nt * 8 + g) * 80 + ks * 16 + 4 * tg);
            mma16(acc1[nt], alo.x, ahi.x, alo.y, ahi.y, bb.x, bb.y);
        }
    }

    // ---- fuse: acc1 -> stage-2 A fragments in registers (bias + relu + cvt) ----
    uint32_t aF[16][4];
    #pragma unroll
    for (int ck = 0; ck < 16; ck++) {
        int c0 = 16 * ck + 2 * tg;       // cols of acc1[2ck]
        int c1 = c0 + 8;                 // cols of acc1[2ck+1]
        float b00 = sb3[c0], b01 = sb3[c0 + 1];
        float b10 = sb3[c1], b11 = sb3[c1 + 1];
        aF[ck][0] = pack2(fmaxf(acc1[2*ck  ][0] + b00, 0.f), fmaxf(acc1[2*ck  ][1] + b01, 0.f));
        aF[ck][1] = pack2(fmaxf(acc1[2*ck  ][2] + b00, 0.f), fmaxf(acc1[2*ck  ][3] + b01, 0.f));
        aF[ck][2] = pack2(fmaxf(acc1[2*ck+1][0] + b10, 0.f), fmaxf(acc1[2*ck+1][1] + b11, 0.f));
        aF[ck][3] = pack2(fmaxf(acc1[2*ck+1][2] + b10, 0.f), fmaxf(acc1[2*ck+1][3] + b11, 0.f));
    }

    asm volatile("cp.async.wait_group 0;" ::: "memory");
    __syncthreads();

    // ---- stage 2: Y = H @ W4^T (A from registers, B from smem; no syncs) ----
    float acc2[32][4];
    #pragma unroll
    for (int nt = 0; nt < 32; nt++)
        #pragma unroll
        for (int q = 0; q < 4; q++) acc2[nt][q] = 0.f;

    #pragma unroll 4
    for (int ck = 0; ck < 16; ck++) {
        uint32_t a0 = aF[ck][0], a1 = aF[ck][1], a2 = aF[ck][2], a3 = aF[ck][3];
        #pragma unroll
        for (int nt = 0; nt < 32; nt++) {
            uint2 bb = *(const uint2*)(sW4 + (nt * 8 + g) * 272 + ck * 16 + 4 * tg);
            mma16(acc2[nt], a0, a1, a2, a3, bb.x, bb.y);
        }
    }

    // ---- epilogue: +b4, quad-shfl row sumsq, L2 norm, store ----
    float s_lo = 0.f, s_hi = 0.f;
    #pragma unroll
    for (int nt = 0; nt < 32; nt++) {
        int col = nt * 8 + 2 * tg;
        float b0 = sb4[col], b1 = sb4[col + 1];
        acc2[nt][0] += b0; acc2[nt][1] += b1;
        acc2[nt][2] += b0; acc2[nt][3] += b1;
        s_lo += acc2[nt][0] * acc2[nt][0] + acc2[nt][1] * acc2[nt][1];
        s_hi += acc2[nt][2] * acc2[nt][2] + acc2[nt][3] * acc2[nt][3];
    }
    s_lo += __shfl_xor_sync(0xffffffffu, s_lo, 1);
    s_lo += __shfl_xor_sync(0xffffffffu, s_lo, 2);
    s_hi += __shfl_xor_sync(0xffffffffu, s_hi, 1);
    s_hi += __shfl_xor_sync(0xffffffffu, s_hi, 2);
    float rn_lo = 1.f / (sqrtf(s_lo) + 1e-7f);
    float rn_hi = 1.f / (sqrtf(s_hi) + 1e-7f);

    long r_lo = row0 + rw0 + g;
    long r_hi = r_lo + 8;
    #pragma unroll
    for (int nt = 0; nt < 32; nt++) {
        int col = nt * 8 + 2 * tg;
        *(float2*)(out1 + r_lo * 256 + col) =
            make_float2(acc2[nt][0] * rn_lo, acc2[nt][1] * rn_lo);
        *(float2*)(out1 + r_hi * 256 + col) =
            make_float2(acc2[nt][2] * rn_hi, acc2[nt][3] * rn_hi);
    }
}

// ---------------- host launcher ----------------
extern "C" void kernel_launch(void* const* d_in, const int* in_sizes, int n_in,
                              void* d_out, int out_size) {
    const float* feat0 = (const float*)d_in[0];
    const float* feat1 = (const float*)d_in[1];
    const float* W1    = (const float*)d_in[2];
    const float* b1    = (const float*)d_in[3];
    const float* gamma = (const float*)d_in[4];
    const float* beta  = (const float*)d_in[5];
    const float* W2    = (const float*)d_in[6];
    const float* b2    = (const float*)d_in[7];
    const float* W3    = (const float*)d_in[8];
    const float* b3    = (const float*)d_in[9];
    const float* W4    = (const float*)d_in[10];
    const float* b4    = (const float*)d_in[11];
    const int* patch_id0 = (const int*)d_in[12];
    const int* patch_id1 = (const int*)d_in[13];
    const int* local_id0 = (const int*)d_in[14];
    const int* local_id1 = (const int*)d_in[15];
    (void)in_sizes; (void)n_in; (void)out_size;

    float* out0 = (float*)d_out;
    float* out1 = out0 + (long)NS0 * O0;

    float*  fr0; cudaGetSymbolAddress((void**)&fr0, g_fr0);
    float*  fr1; cudaGetSymbolAddress((void**)&fr1, g_fr1);
    float*  H;   cudaGetSymbolAddress((void**)&H,   g_H);
    __half* X0h; cudaGetSymbolAddress((void**)&X0h, g_X0h);
    __half* Ahp; cudaGetSymbolAddress((void**)&Ahp, g_Ah);
    __half* W1h; cudaGetSymbolAddress((void**)&W1h, g_W1h);
    __half* W2h; cudaGetSymbolAddress((void**)&W2h, g_W2h);

    cudaFuncSetAttribute(mlp_fp16_kernel, cudaFuncAttributeMaxDynamicSharedMemorySize,
                         MLP_SMEM_BYTES);

    // transposes
    {
        dim3 g1(HW1 / 32, BB);
        transpose_feat1<<<g1, 256>>>(feat1, fr1);
        dim3 g0(C0 / 32, BB);
        transpose_feat0<<<g0, 256>>>(feat0, fr0);
    }

    // fused weight conversion
    cvt_all<<<848, 1024>>>(W1, W2, W3, W4);

    // sampling
    sample0_kernel<<<NS0, 256>>>(patch_id0, local_id0);
    sample1_kernel<<<NS1, 128>>>(patch_id1, local_id1);

    // path0
    {
        dim3 g(H1 / 64, NS0 / 128);
        gemm_fp16<<<g, 256>>>(X0h, W1h, b1, H, NS0, H1, C0);
    }
    bnstatsA_kernel<<<32, 256>>>();
    bnstatsB_kernel<<<4, 256>>>(gamma, beta);
    bnapply_kernel<<<1024, 256>>>();
    {
        dim3 g(O0 / 64, NS0 / 128);
        gemm_fp16<<<g, 256>>>(Ahp, W2h, b2, out0, NS0, O0, H1);
    }

    // path1
    mlp_fp16_kernel<<<ROWS1 / 128, 256, MLP_SMEM_BYTES>>>(b3, b4, out1);
}

// round 8
// speedup vs baseline: 5.8427x; 1.0789x over previous
#include <cuda_runtime.h>
#include <cuda_fp16.h>
#include <math.h>
#include <stdint.h>

// ---------------- problem constants ----------------
#define BB   8
#define C0   512
#define HW0  64
#define N0   64
#define L0   8
#define KN0  4
#define C1   64
#define HW1  16384
#define N1   512
#define L1   80
#define KN1  40
#define M1   41
#define NS0  (BB*N0)     // 512
#define NS1  (BB*N1)     // 4096
#define ROWS1 (NS1*M1)   // 167936
#define H1   1024
#define O0   256
#define O1   256
#define NTILES (ROWS1/128)   // 1312
#define PGRID  148

// ---------------- scratch ----------------
__device__ float  g_fr0[BB*HW0*C0];
__device__ float  g_fr1[BB*HW1*C1];
__device__ float  g_H [NS0*H1];
__device__ float  g_scale[H1];
__device__ float  g_shift[H1];
__device__ float  g_bnp[2*32*H1];
__device__ __half g_X0h[NS0*C0];
__device__ __half g_Ah [NS0*H1];
__device__ __half g_W1h[H1*C0];
__device__ __half g_W2h[O0*H1];
__device__ __half g_W3h[256*64];
__device__ __half g_W4h[256*256];
__device__ __half g_X1h[(long)ROWS1*C1];

// ---------------- fp16 mma helpers ----------------
__device__ __forceinline__ int reord16(int k) { return ((k & 7) >> 1) * 4 + ((k >> 3) & 1) * 2 + (k & 1); }
__device__ __forceinline__ int reordk(int k)  { return (k & ~15) + reord16(k & 15); }

__device__ __forceinline__ void mma16(float acc[4], uint32_t a0, uint32_t a1,
                                      uint32_t a2, uint32_t a3, uint32_t b0, uint32_t b1) {
    asm volatile(
        "mma.sync.aligned.m16n8k16.row.col.f32.f16.f16.f32 "
        "{%0,%1,%2,%3}, {%4,%5,%6,%7}, {%8,%9}, {%0,%1,%2,%3};"
        : "+f"(acc[0]), "+f"(acc[1]), "+f"(acc[2]), "+f"(acc[3])
        : "r"(a0), "r"(a1), "r"(a2), "r"(a3), "r"(b0), "r"(b1));
}
__device__ __forceinline__ uint32_t pack2(float a, float b) {
    __half2 h = __floats2half2_rn(a, b);
    return *(uint32_t*)&h;
}
__device__ __forceinline__ void cp16(uint32_t dst, const void* src) {
    asm volatile("cp.async.cg.shared.global [%0], [%1], 16;" :: "r"(dst), "l"(src));
}
#define CP_COMMIT() asm volatile("cp.async.commit_group;" ::: "memory")
#define CP_WAIT1()  asm volatile("cp.async.wait_group 1;" ::: "memory")

// ---------------- fused weight conversions ----------------
#define S0E 524288L
#define S1E 786432L
#define S2E 802816L
#define S3E 868352L
__global__ void cvt_all(const float* __restrict__ W1, const float* __restrict__ W2,
                        const float* __restrict__ W3, const float* __restrict__ W4) {
    long i = (long)blockIdx.x * blockDim.x + threadIdx.x;
    if (i >= S3E) return;
    const float* src; __half* dst; long base; int mask;
    if (i < S0E)      { src = W1; dst = g_W1h; base = 0;   mask = 511; }
    else if (i < S1E) { src = W2; dst = g_W2h; base = S0E; mask = 1023; }
    else if (i < S2E) { src = W3; dst = g_W3h; base = S1E; mask = 63; }
    else              { src = W4; dst = g_W4h; base = S2E; mask = 255; }
    long j = i - base;
    int k = (int)j & mask;
    dst[j - k + reordk(k)] = __float2half_rn(src[j]);
}

// ---------------- coalesced transposes ----------------
__global__ void transpose_feat1(const float* __restrict__ f, float* __restrict__ out) {
    __shared__ float sm[64 * 33];
    int b = blockIdx.y;
    int p0 = blockIdx.x * 32;
    int t = threadIdx.x;
    int pp = t & 31, c0 = t >> 5;
    #pragma unroll
    for (int i = 0; i < 8; i++) {
        int c = c0 + i * 8;
        sm[c * 33 + pp] = f[((long)b * 64 + c) * 16384 + p0 + pp];
    }
    __syncthreads();
    #pragma unroll
    for (int i = 0; i < 8; i++) {
        int idx = i * 256 + t;
        int p = idx >> 6, c = idx & 63;
        out[((long)b * 16384 + p0 + p) * 64 + c] = sm[c * 33 + p];
    }
}
__global__ void transpose_feat0(const float* __restrict__ f, float* __restrict__ out) {
    __shared__ float sm[32 * 65];
    int b = blockIdx.y;
    int c0 = blockIdx.x * 32;
    int t = threadIdx.x;
    int p = t & 63, cc = t >> 6;
    #pragma unroll
    for (int i = 0; i < 8; i++) {
        int c = cc + i * 4;
        sm[c * 65 + p] = f[((long)b * 512 + c0 + c) * 64 + p];
    }
    __syncthreads();
    #pragma unroll
    for (int i = 0; i < 8; i++) {
        int idx = i * 256 + t;
        int p2 = idx >> 5, c = idx & 31;
        out[((long)b * 64 + p2) * 512 + c0 + c] = sm[c * 65 + p2];
    }
}

// ---------------- path0 sampling ----------------
__global__ void sample0_kernel(const int* __restrict__ pid, const int* __restrict__ lid) {
    __shared__ float cen[C0];
    __shared__ float sim[L0];
    __shared__ int   rowsS[L0];
    __shared__ int   chosen[KN0];
    int blk = blockIdx.x;
    int b = blk / N0, n = blk % N0;
    int t = threadIdx.x;
    int p = pid[n];
    const float* base = g_fr0 + (long)b * HW0 * C0;
    const float* cptr = base + (long)p * C0;
    for (int c = t; c < C0; c += 256) cen[c] = cptr[c];
    if (t < L0) rowsS[t] = lid[n * L0 + t];
    __syncthreads();
    int w = t >> 5, lane = t & 31;
    {
        const float* lp = base + (long)rowsS[w] * C0;
        float dot = 0.f, ss = 0.f;
        for (int c = lane; c < C0; c += 32) {
            float v = lp[c];
            dot += v * cen[c];
            ss  += v * v;
        }
        for (int o = 16; o > 0; o >>= 1) {
            dot += __shfl_down_sync(0xffffffffu, dot, o);
            ss  += __shfl_down_sync(0xffffffffu, ss,  o);
        }
        if (lane == 0) sim[w] = dot / fmaxf(sqrtf(ss), 1e-12f);
    }
    __syncthreads();
    if (t < L0) {
        int l = t;
        float v = sim[l];
        int cnt = 0;
        #pragma unroll
        for (int j = 0; j < L0; j++) {
            float u = sim[j];
            cnt += (u > v || (u == v && j < l)) ? 1 : 0;
        }
        if (cnt < KN0) chosen[cnt] = rowsS[l];
    }
    __syncthreads();
    for (int c = t; c < C0; c += 256) {
        float acc = cen[c];
        #pragma unroll
        for (int r = 0; r < KN0; r++) acc += base[(long)chosen[r] * C0 + c];
        g_X0h[(long)blk * C0 + reordk(c)] = __float2half_rn(acc * 0.2f);
    }
}

// ---------------- path1 sampling ----------------
__global__ void sample1_kernel(const int* __restrict__ pid, const int* __restrict__ lid) {
    __shared__ float cen[C1];
    __shared__ float loc[L1 * 68];
    __shared__ float sim[L1];
    __shared__ int   rowsS[L1];
    __shared__ int   sel[KN1];
    int blk = blockIdx.x;
    int b = blk / N1, n = blk % N1;
    int t = threadIdx.x;
    const float* base = g_fr1 + (long)b * HW1 * C1;
    int p = pid[n];
    if (t < C1) cen[t] = base[(long)p * C1 + t];
    if (t < L1) rowsS[t] = lid[n * L1 + t];
    __syncthreads();
    #pragma unroll 2
    for (int i = t; i < L1 * 16; i += 128) {
        int l = i >> 4, c4 = i & 15;
        float4 v = *(const float4*)(base + (long)rowsS[l] * C1 + c4 * 4);
        *(float4*)(loc + l * 68 + c4 * 4) = v;
    }
    __syncthreads();
    if (t < L1) {
        const float4* lp = (const float4*)(loc + t * 68);
        const float4* cp = (const float4*)cen;
        float dot = 0.f, ss = 0.f;
        #pragma unroll
        for (int c4 = 0; c4 < 16; c4++) {
            float4 v = lp[c4], cv = cp[c4];
            dot += v.x * cv.x + v.y * cv.y + v.z * cv.z + v.w * cv.w;
            ss  += v.x * v.x + v.y * v.y + v.z * v.z + v.w * v.w;
        }
        sim[t] = dot / fmaxf(sqrtf(ss), 1e-12f);
    }
    __syncthreads();
    if (t < L1) {
        int l = t;
        float v = sim[l];
        int cnt = 0;
        #pragma unroll
        for (int j = 0; j < L1; j++) {
            float u = sim[j];
            cnt += (u > v || (u == v && j < l)) ? 1 : 0;
        }
        if (cnt < KN1) sel[cnt] = l;
    }
    __syncthreads();
    long obase = (long)blk * M1 * C1;
    #pragma unroll 2
    for (int idx = t; idx < M1 * C1; idx += 128) {
        int m = idx >> 6, c = idx & 63;
        float v = (m == 0) ? cen[c] : loc[sel[m - 1] * 68 + c];
        g_X1h[obase + m * C1 + reordk(c)] = __float2half_rn(v);
    }
}

// ---------------- fp16 mma GEMM (path0) ----------------
__global__ __launch_bounds__(256) void gemm_fp16(const __half* __restrict__ Ah,
                                                 const __half* __restrict__ Bh,
                                                 const float* __restrict__ bias,
                                                 float* __restrict__ C,
                                                 int M, int N, int K) {
    __shared__ __half sA[128 * 48];
    __shared__ __half sB[64 * 48];
    int t = threadIdx.x;
    int w = t >> 5, lane = t & 31;
    int g = lane >> 2, tg = lane & 3;
    int rw0 = w * 16;
    int m0 = blockIdx.y * 128, n0 = blockIdx.x * 64;

    float acc[8][4];
    #pragma unroll
    for (int nt = 0; nt < 8; nt++)
        #pragma unroll
        for (int q = 0; q < 4; q++) acc[nt][q] = 0.f;

    for (int kc = 0; kc < K / 32; kc++) {
        __syncthreads();
        #pragma unroll
        for (int i = 0; i < 2; i++) {
            int idx = i * 256 + t;
            int r = idx >> 2, q = idx & 3;
            *(uint4*)(sA + r * 48 + q * 8) =
                *(const uint4*)(Ah + (long)(m0 + r) * K + kc * 32 + q * 8);
        }
        {
            int r = t >> 2, q = t & 3;
            *(uint4*)(sB + r * 48 + q * 8) =
                *(const uint4*)(Bh + (long)(n0 + r) * K + kc * 32 + q * 8);
        }
        __syncthreads();
        #pragma unroll
        for (int ks = 0; ks < 2; ks++) {
            uint2 alo = *(const uint2*)(sA + (rw0 + g) * 48 + ks * 16 + 4 * tg);
            uint2 ahi = *(const uint2*)(sA + (rw0 + g + 8) * 48 + ks * 16 + 4 * tg);
            #pragma unroll
            for (int nt = 0; nt < 8; nt++) {
                uint2 bb = *(const uint2*)(sB + (nt * 8 + g) * 48 + ks * 16 + 4 * tg);
                mma16(acc[nt], alo.x, ahi.x, alo.y, ahi.y, bb.x, bb.y);
            }
        }
    }
    #pragma unroll
    for (int nt = 0; nt < 8; nt++) {
        int col = n0 + nt * 8 + 2 * tg;
        float bj0 = bias[col], bj1 = bias[col + 1];
        C[(long)(m0 + rw0 + g    ) * N + col    ] = acc[nt][0] + bj0;
        C[(long)(m0 + rw0 + g    ) * N + col + 1] = acc[nt][1] + bj1;
        C[(long)(m0 + rw0 + g + 8) * N + col    ] = acc[nt][2] + bj0;
        C[(long)(m0 + rw0 + g + 8) * N + col + 1] = acc[nt][3] + bj1;
    }
}

// ---------------- BN ----------------
__global__ void bnstatsA_kernel() {
    int b = blockIdx.x;
    int t = threadIdx.x;
    float s[4] = {0.f, 0.f, 0.f, 0.f}, ss[4] = {0.f, 0.f, 0.f, 0.f};
    for (int r = 0; r < 16; r++) {
        const float* row = g_H + (long)(b * 16 + r) * H1;
        #pragma unroll
        for (int j = 0; j < 4; j++) {
            float v = row[t + 256 * j];
            s[j] += v; ss[j] += v * v;
        }
    }
    #pragma unroll
    for (int j = 0; j < 4; j++) {
        g_bnp[b * H1 + t + 256 * j] = s[j];
        g_bnp[32 * H1 + b * H1 + t + 256 * j] = ss[j];
    }
}
__global__ void bnstatsB_kernel(const float* __restrict__ gamma, const float* __restrict__ beta) {
    int j = blockIdx.x * 256 + threadIdx.x;
    float s = 0.f, ss = 0.f;
    for (int b = 0; b < 32; b++) {
        s  += g_bnp[b * H1 + j];
        ss += g_bnp[32 * H1 + b * H1 + j];
    }
    float mu  = s / NS0;
    float var = ss / NS0 - mu * mu;
    float sc  = gamma[j] / sqrtf(var + 1e-5f);
    g_scale[j] = sc;
    g_shift[j] = beta[j] - mu * sc;
}
__global__ void bnapply_kernel() {
    long total = (long)NS0 * H1;
    for (long i = (long)blockIdx.x * blockDim.x + threadIdx.x; i < total;
         i += (long)gridDim.x * blockDim.x) {
        int j = (int)(i % H1);
        float v = g_H[i] * g_scale[j] + g_shift[j];
        g_Ah[i - j + reordk(j)] = __float2half_rn(fmaxf(v, 0.f));
    }
}

// ================= path1 MLP: PERSISTENT register-fused B2B fp16 mma =================
// smem halves: sX0 [0,10240) ; sX1 [10240,20480) ; sW3 [20480,40960) 256x80 ;
//              sW4 [40960,110592) 256x272 ; floats after: sb3[256], sb4[256]
#define PH_X0  0
#define PH_X1  10240
#define PH_W3  20480
#define PH_W4  40960
#define PH_F   110592
#define MLP_SMEM_BYTES (PH_F*2 + 512*4)

__global__ __launch_bounds__(256, 1) void mlp_fp16_kernel(const float* __restrict__ b3,
                                                          const float* __restrict__ b4,
                                                          float* __restrict__ out1) {
    extern __shared__ __half sh[];
    __half* sW3 = sh + PH_W3;
    __half* sW4 = sh + PH_W4;
    float*  sb3 = (float*)(sh + PH_F);
    float*  sb4 = sb3 + 256;

    int t = threadIdx.x;
    int lane = t & 31;
    int g = lane >> 2, tg = lane & 3;
    int rw0 = (t >> 5) * 16;
    int bid = blockIdx.x;

    uint32_t sbase = (uint32_t)__cvta_generic_to_shared(sh);
    uint32_t xoff[2] = { sbase + PH_X0 * 2u, sbase + PH_X1 * 2u };

    // group 0: X[tile0] + W3 + W4
    {
        long t0 = bid;
        #pragma unroll
        for (int i = t; i < 1024; i += 256) {
            int r = i >> 3, q = i & 7;
            cp16(xoff[0] + (uint32_t)(r * 80 + q * 8) * 2, g_X1h + (t0 * 128 + r) * 64 + q * 8);
        }
        #pragma unroll
        for (int i = t; i < 2048; i += 256) {
            int r = i >> 3, q = i & 7;
            cp16(sbase + (uint32_t)(PH_W3 + r * 80 + q * 8) * 2, g_W3h + (long)r * 64 + q * 8);
        }
        #pragma unroll 4
        for (int i = t; i < 8192; i += 256) {
            int r = i >> 5, q = i & 31;
            cp16(sbase + (uint32_t)(PH_W4 + r * 272 + q * 8) * 2, g_W4h + (long)r * 256 + q * 8);
        }
        CP_COMMIT();
    }
    // group 1: X[tile1] (if any)
    {
        long t1 = bid + PGRID;
        if (t1 < NTILES) {
            #pragma unroll
            for (int i = t; i < 1024; i += 256) {
                int r = i >> 3, q = i & 7;
                cp16(xoff[1] + (uint32_t)(r * 80 + q * 8) * 2, g_X1h + (t1 * 128 + r) * 64 + q * 8);
            }
        }
        CP_COMMIT();
    }
    sb3[t] = b3[t];
    sb4[t] = b4[t];

    int j = 0;
    for (long tile = bid; tile < NTILES; tile += PGRID, j++) {
        int b = j & 1;
        __half* sX = sh + (b ? PH_X1 : PH_X0);
        long row0 = tile * 128;

        CP_WAIT1();           // invariant: 2 groups pending at tile top; current X landed
        __syncthreads();

        // ---- stage 1 ----
        float acc1[32][4];
        #pragma unroll
        for (int nt = 0; nt < 32; nt++)
            #pragma unroll
            for (int q = 0; q < 4; q++) acc1[nt][q] = 0.f;

        #pragma unroll
        for (int ks = 0; ks < 4; ks++) {
            uint2 alo = *(const uint2*)(sX + (rw0 + g) * 80 + ks * 16 + 4 * tg);
            uint2 ahi = *(const uint2*)(sX + (rw0 + g + 8) * 80 + ks * 16 + 4 * tg);
            #pragma unroll
            for (int nt = 0; nt < 32; nt++) {
                uint2 bb = *(const uint2*)(sW3 + (nt * 8 + g) * 80 + ks * 16 + 4 * tg);
                mma16(acc1[nt], alo.x, ahi.x, alo.y, ahi.y, bb.x, bb.y);
            }
        }
        __syncthreads();      // all warps done reading sX buffer b

        // prefetch X[tile + 2*PGRID] into buffer b
        {
            long tn = tile + 2 * PGRID;
            if (tn < NTILES) {
                #pragma unroll
                for (int i = t; i < 1024; i += 256) {
                    int r = i >> 3, q = i & 7;
                    cp16(xoff[b] + (uint32_t)(r * 80 + q * 8) * 2,
                         g_X1h + (tn * 128 + r) * 64 + q * 8);
                }
            }
            CP_COMMIT();      // keep group invariant even when empty
        }

        // ---- fuse: acc1 -> stage-2 A fragments ----
        uint32_t aF[16][4];
        #pragma unroll
        for (int ck = 0; ck < 16; ck++) {
            int c0 = 16 * ck + 2 * tg;
            int c1 = c0 + 8;
            float b00 = sb3[c0], b01 = sb3[c0 + 1];
            float b10 = sb3[c1], b11 = sb3[c1 + 1];
            aF[ck][0] = pack2(fmaxf(acc1[2*ck  ][0] + b00, 0.f), fmaxf(acc1[2*ck  ][1] + b01, 0.f));
            aF[ck][1] = pack2(fmaxf(acc1[2*ck  ][2] + b00, 0.f), fmaxf(acc1[2*ck  ][3] + b01, 0.f));
            aF[ck][2] = pack2(fmaxf(acc1[2*ck+1][0] + b10, 0.f), fmaxf(acc1[2*ck+1][1] + b11, 0.f));
            aF[ck][3] = pack2(fmaxf(acc1[2*ck+1][2] + b10, 0.f), fmaxf(acc1[2*ck+1][3] + b11, 0.f));
        }

        // ---- stage 2 (sync-free; W4 resident) ----
        float acc2[32][4];
        #pragma unroll
        for (int nt = 0; nt < 32; nt++)
            #pragma unroll
            for (int q = 0; q < 4; q++) acc2[nt][q] = 0.f;

        #pragma unroll 4
        for (int ck = 0; ck < 16; ck++) {
            uint32_t a0 = aF[ck][0], a1 = aF[ck][1], a2 = aF[ck][2], a3 = aF[ck][3];
            #pragma unroll
            for (int nt = 0; nt < 32; nt++) {
                uint2 bb = *(const uint2*)(sW4 + (nt * 8 + g) * 272 + ck * 16 + 4 * tg);
                mma16(acc2[nt], a0, a1, a2, a3, bb.x, bb.y);
            }
        }

        // ---- epilogue ----
        float s_lo = 0.f, s_hi = 0.f;
        #pragma unroll
        for (int nt = 0; nt < 32; nt++) {
            int col = nt * 8 + 2 * tg;
            float b0 = sb4[col], b1 = sb4[col + 1];
            acc2[nt][0] += b0; acc2[nt][1] += b1;
            acc2[nt][2] += b0; acc2[nt][3] += b1;
            s_lo += acc2[nt][0] * acc2[nt][0] + acc2[nt][1] * acc2[nt][1];
            s_hi += acc2[nt][2] * acc2[nt][2] + acc2[nt][3] * acc2[nt][3];
        }
        s_lo += __shfl_xor_sync(0xffffffffu, s_lo, 1);
        s_lo += __shfl_xor_sync(0xffffffffu, s_lo, 2);
        s_hi += __shfl_xor_sync(0xffffffffu, s_hi, 1);
        s_hi += __shfl_xor_sync(0xffffffffu, s_hi, 2);
        float rn_lo = 1.f / (sqrtf(s_lo) + 1e-7f);
        float rn_hi = 1.f / (sqrtf(s_hi) + 1e-7f);

        long r_lo = row0 + rw0 + g;
        long r_hi = r_lo + 8;
        #pragma unroll
        for (int nt = 0; nt < 32; nt++) {
            int col = nt * 8 + 2 * tg;
            *(float2*)(out1 + r_lo * 256 + col) =
                make_float2(acc2[nt][0] * rn_lo, acc2[nt][1] * rn_lo);
            *(float2*)(out1 + r_hi * 256 + col) =
                make_float2(acc2[nt][2] * rn_hi, acc2[nt][3] * rn_hi);
        }
    }
}

// ---------------- host launcher ----------------
extern "C" void kernel_launch(void* const* d_in, const int* in_sizes, int n_in,
                              void* d_out, int out_size) {
    const float* feat0 = (const float*)d_in[0];
    const float* feat1 = (const float*)d_in[1];
    const float* W1    = (const float*)d_in[2];
    const float* b1    = (const float*)d_in[3];
    const float* gamma = (const float*)d_in[4];
    const float* beta  = (const float*)d_in[5];
    const float* W2    = (const float*)d_in[6];
    const float* b2    = (const float*)d_in[7];
    const float* W3    = (const float*)d_in[8];
    const float* b3    = (const float*)d_in[9];
    const float* W4    = (const float*)d_in[10];
    const float* b4    = (const float*)d_in[11];
    const int* patch_id0 = (const int*)d_in[12];
    const int* patch_id1 = (const int*)d_in[13];
    const int* local_id0 = (const int*)d_in[14];
    const int* local_id1 = (const int*)d_in[15];
    (void)in_sizes; (void)n_in; (void)out_size;

    float* out0 = (float*)d_out;
    float* out1 = out0 + (long)NS0 * O0;

    float*  fr0; cudaGetSymbolAddress((void**)&fr0, g_fr0);
    float*  fr1; cudaGetSymbolAddress((void**)&fr1, g_fr1);
    float*  H;   cudaGetSymbolAddress((void**)&H,   g_H);
    __half* X0h; cudaGetSymbolAddress((void**)&X0h, g_X0h);
    __half* Ahp; cudaGetSymbolAddress((void**)&Ahp, g_Ah);
    __half* W1h; cudaGetSymbolAddress((void**)&W1h, g_W1h);
    __half* W2h; cudaGetSymbolAddress((void**)&W2h, g_W2h);

    cudaFuncSetAttribute(mlp_fp16_kernel, cudaFuncAttributeMaxDynamicSharedMemorySize,
                         MLP_SMEM_BYTES);

    // transposes
    {
        dim3 g1(HW1 / 32, BB);
        transpose_feat1<<<g1, 256>>>(feat1, fr1);
        dim3 g0(C0 / 32, BB);
        transpose_feat0<<<g0, 256>>>(feat0, fr0);
    }

    // fused weight conversion
    cvt_all<<<848, 1024>>>(W1, W2, W3, W4);

    // sampling
    sample0_kernel<<<NS0, 256>>>(patch_id0, local_id0);
    sample1_kernel<<<NS1, 128>>>(patch_id1, local_id1);

    // path0
    {
        dim3 g(H1 / 64, NS0 / 128);
        gemm_fp16<<<g, 256>>>(X0h, W1h, b1, H, NS0, H1, C0);
    }
    bnstatsA_kernel<<<32, 256>>>();
    bnstatsB_kernel<<<4, 256>>>(gamma, beta);
    bnapply_kernel<<<1024, 256>>>();
    {
        dim3 g(O0 / 64, NS0 / 128);
        gemm_fp16<<<g, 256>>>(Ahp, W2h, b2, out0, NS0, O0, H1);
    }

    // path1: persistent fused MLP
    mlp_fp16_kernel<<<PGRID, 256, MLP_SMEM_BYTES>>>(b3, b4, out1);
}